// round 1
// baseline (speedup 1.0000x reference)
#include <cuda_runtime.h>
#include <math.h>

// Shapes (fixed by the problem)
#define BSZ 8
#define CH  256
#define HW  4096            // 64*64 tokens
#define GRP 32
#define CPG 8               // channels per group

// ---------------- scratch (static device globals; no runtime alloc) --------
__device__ float g_hn[BSZ * CH * HW];                 // 32 MB
__device__ float g_q [BSZ * CH * HW];
__device__ float g_k [BSZ * CH * HW];
__device__ float g_v [BSZ * CH * HW];
__device__ float g_ao[BSZ * CH * HW];
__device__ float g_s [(size_t)BSZ * HW * HW];         // 512 MB scores

// ============================ GroupNorm =====================================
__global__ void __launch_bounds__(256) gn_kernel(const float* __restrict__ x,
                                                 const float* __restrict__ sc,
                                                 const float* __restrict__ bi) {
    int b = blockIdx.x >> 5;
    int g = blockIdx.x & 31;
    const float* xp = x    + ((size_t)b * CH + g * CPG) * HW;
    float*       op = g_hn + ((size_t)b * CH + g * CPG) * HW;
    int t = threadIdx.x;
    const int TOT = CPG * HW;   // 32768

    float s = 0.f, s2 = 0.f;
    for (int i = t * 4; i < TOT; i += 1024) {
        float4 v = *(const float4*)&xp[i];
        s  += v.x + v.y + v.z + v.w;
        s2 += v.x * v.x + v.y * v.y + v.z * v.z + v.w * v.w;
    }
    __shared__ float rs[256], rs2[256];
    rs[t] = s; rs2[t] = s2;
    __syncthreads();
    for (int o = 128; o > 0; o >>= 1) {
        if (t < o) { rs[t] += rs[t + o]; rs2[t] += rs2[t + o]; }
        __syncthreads();
    }
    float mean = rs[0] * (1.0f / TOT);
    float var  = rs2[0] * (1.0f / TOT) - mean * mean;
    float inv  = rsqrtf(var + 1e-6f);

    for (int i = t * 4; i < TOT; i += 1024) {
        int c = g * CPG + (i >> 12);                  // i/4096; const within float4
        float a  = sc[c] * inv;
        float bb = bi[c] - mean * a;
        float4 v = *(const float4*)&xp[i];
        float4 o;
        o.x = v.x * a + bb; o.y = v.y * a + bb;
        o.z = v.z * a + bb; o.w = v.w * a + bb;
        *(float4*)&op[i] = o;
    }
}

// ===================== QKV GEMM: out[o][n] = W[o][c]*hn[c][n] + b[o] ========
// NN form: A row-major [M=256][K=256], B row-major [K=256][N=4096]
__global__ void __launch_bounds__(256) qkv_kernel(const float* __restrict__ wq,
                                                  const float* __restrict__ bq,
                                                  const float* __restrict__ wk,
                                                  const float* __restrict__ bk,
                                                  const float* __restrict__ wv,
                                                  const float* __restrict__ bv) {
    int which = blockIdx.y >> 1;
    int m0 = (blockIdx.y & 1) * 128;
    int n0 = blockIdx.x * 128;
    int b  = blockIdx.z;
    const float* W    = (which == 0) ? wq : (which == 1) ? wk : wv;
    const float* bias = (which == 0) ? bq : (which == 1) ? bk : bv;
    float*       out  = ((which == 0) ? g_q : (which == 1) ? g_k : g_v) + (size_t)b * CH * HW;
    const float* X    = g_hn + (size_t)b * CH * HW;

    __shared__ float As[8][128];
    __shared__ float Bs[8][128];
    float acc[8][8];
#pragma unroll
    for (int i = 0; i < 8; i++)
#pragma unroll
        for (int j = 0; j < 8; j++) acc[i][j] = 0.f;

    int t = threadIdx.x, tx = t & 15, ty = t >> 4;
    int ar = t >> 1, ac = (t & 1) * 4;
    int br = t >> 5, bc = (t & 31) * 4;

    for (int k0 = 0; k0 < CH; k0 += 8) {
        float4 av = *(const float4*)&W[(m0 + ar) * CH + k0 + ac];
        As[ac + 0][ar] = av.x; As[ac + 1][ar] = av.y;
        As[ac + 2][ar] = av.z; As[ac + 3][ar] = av.w;
        *(float4*)&Bs[br][bc] = *(const float4*)&X[(size_t)(k0 + br) * HW + n0 + bc];
        __syncthreads();
#pragma unroll
        for (int kk = 0; kk < 8; kk++) {
            float a[8], bb[8];
            *(float4*)(a)     = *(const float4*)&As[kk][ty * 8];
            *(float4*)(a + 4) = *(const float4*)&As[kk][ty * 8 + 4];
            *(float4*)(bb)     = *(const float4*)&Bs[kk][tx * 8];
            *(float4*)(bb + 4) = *(const float4*)&Bs[kk][tx * 8 + 4];
#pragma unroll
            for (int i = 0; i < 8; i++)
#pragma unroll
                for (int j = 0; j < 8; j++) acc[i][j] += a[i] * bb[j];
        }
        __syncthreads();
    }
#pragma unroll
    for (int i = 0; i < 8; i++) {
        int row = m0 + ty * 8 + i;
        float bv = bias[row];
        float4 o0 = {acc[i][0] + bv, acc[i][1] + bv, acc[i][2] + bv, acc[i][3] + bv};
        float4 o1 = {acc[i][4] + bv, acc[i][5] + bv, acc[i][6] + bv, acc[i][7] + bv};
        size_t idx = (size_t)row * HW + n0 + tx * 8;
        *(float4*)&out[idx]     = o0;
        *(float4*)&out[idx + 4] = o1;
    }
}

// ======== Scores: S[n][m] = (1/16) * sum_c q[c][n] k[c][m]  (TN form) ======
__global__ void __launch_bounds__(256) scores_kernel() {
    int m0 = blockIdx.y * 128;   // query (row) tile
    int n0 = blockIdx.x * 128;   // key (col) tile
    int b  = blockIdx.z;
    const float* Q  = g_q + (size_t)b * CH * HW;
    const float* Kp = g_k + (size_t)b * CH * HW;
    float*       S  = g_s + (size_t)b * HW * HW;

    __shared__ float As[8][128];
    __shared__ float Bs[8][128];
    float acc[8][8];
#pragma unroll
    for (int i = 0; i < 8; i++)
#pragma unroll
        for (int j = 0; j < 8; j++) acc[i][j] = 0.f;

    int t = threadIdx.x, tx = t & 15, ty = t >> 4;
    int kr = t >> 5, kc = (t & 31) * 4;

    for (int k0 = 0; k0 < CH; k0 += 8) {
        *(float4*)&As[kr][kc] = *(const float4*)&Q [(size_t)(k0 + kr) * HW + m0 + kc];
        *(float4*)&Bs[kr][kc] = *(const float4*)&Kp[(size_t)(k0 + kr) * HW + n0 + kc];
        __syncthreads();
#pragma unroll
        for (int kk = 0; kk < 8; kk++) {
            float a[8], bb[8];
            *(float4*)(a)     = *(const float4*)&As[kk][ty * 8];
            *(float4*)(a + 4) = *(const float4*)&As[kk][ty * 8 + 4];
            *(float4*)(bb)     = *(const float4*)&Bs[kk][tx * 8];
            *(float4*)(bb + 4) = *(const float4*)&Bs[kk][tx * 8 + 4];
#pragma unroll
            for (int i = 0; i < 8; i++)
#pragma unroll
                for (int j = 0; j < 8; j++) acc[i][j] += a[i] * bb[j];
        }
        __syncthreads();
    }
    const float scale = 0.0625f;  // 256^-0.5
#pragma unroll
    for (int i = 0; i < 8; i++) {
        size_t idx = (size_t)(m0 + ty * 8 + i) * HW + n0 + tx * 8;
        float4 o0 = {acc[i][0] * scale, acc[i][1] * scale, acc[i][2] * scale, acc[i][3] * scale};
        float4 o1 = {acc[i][4] * scale, acc[i][5] * scale, acc[i][6] * scale, acc[i][7] * scale};
        *(float4*)&S[idx]     = o0;
        *(float4*)&S[idx + 4] = o1;
    }
}

// =========================== Row softmax over m =============================
__global__ void __launch_bounds__(256) softmax_kernel() {
    size_t row = blockIdx.x;                 // b*4096 + n
    float* p = g_s + row * (size_t)HW;
    int t = threadIdx.x;

    float4 v[4];
    float mx = -1e30f;
#pragma unroll
    for (int i = 0; i < 4; i++) {
        v[i] = *(const float4*)&p[t * 4 + i * 1024];
        mx = fmaxf(mx, fmaxf(fmaxf(v[i].x, v[i].y), fmaxf(v[i].z, v[i].w)));
    }
    __shared__ float red[256];
    red[t] = mx; __syncthreads();
    for (int o = 128; o > 0; o >>= 1) {
        if (t < o) red[t] = fmaxf(red[t], red[t + o]);
        __syncthreads();
    }
    mx = red[0];
    __syncthreads();

    float sum = 0.f;
#pragma unroll
    for (int i = 0; i < 4; i++) {
        v[i].x = __expf(v[i].x - mx); v[i].y = __expf(v[i].y - mx);
        v[i].z = __expf(v[i].z - mx); v[i].w = __expf(v[i].w - mx);
        sum += v[i].x + v[i].y + v[i].z + v[i].w;
    }
    red[t] = sum; __syncthreads();
    for (int o = 128; o > 0; o >>= 1) {
        if (t < o) red[t] += red[t + o];
        __syncthreads();
    }
    float inv = 1.0f / red[0];
#pragma unroll
    for (int i = 0; i < 4; i++) {
        v[i].x *= inv; v[i].y *= inv; v[i].z *= inv; v[i].w *= inv;
        *(float4*)&p[t * 4 + i * 1024] = v[i];
    }
}

// ======== PV: O[c][n] = sum_m v[c][m] * P[n][m]   (NT form, K=4096) ========
__global__ void __launch_bounds__(256) pv_kernel() {
    int m0 = blockIdx.y * 128;   // c tile (2)
    int n0 = blockIdx.x * 128;   // n tile (32)
    int b  = blockIdx.z;
    const float* V = g_v  + (size_t)b * CH * HW;
    const float* P = g_s  + (size_t)b * HW * HW;
    float*       O = g_ao + (size_t)b * CH * HW;

    __shared__ float As[8][128];
    __shared__ float Bs[8][128];
    float acc[8][8];
#pragma unroll
    for (int i = 0; i < 8; i++)
#pragma unroll
        for (int j = 0; j < 8; j++) acc[i][j] = 0.f;

    int t = threadIdx.x, tx = t & 15, ty = t >> 4;
    int ar = t >> 1, ac = (t & 1) * 4;

    for (int k0 = 0; k0 < HW; k0 += 8) {
        float4 av = *(const float4*)&V[(size_t)(m0 + ar) * HW + k0 + ac];
        As[ac + 0][ar] = av.x; As[ac + 1][ar] = av.y;
        As[ac + 2][ar] = av.z; As[ac + 3][ar] = av.w;
        float4 bv = *(const float4*)&P[(size_t)(n0 + ar) * HW + k0 + ac];
        Bs[ac + 0][ar] = bv.x; Bs[ac + 1][ar] = bv.y;
        Bs[ac + 2][ar] = bv.z; Bs[ac + 3][ar] = bv.w;
        __syncthreads();
#pragma unroll
        for (int kk = 0; kk < 8; kk++) {
            float a[8], bb[8];
            *(float4*)(a)     = *(const float4*)&As[kk][ty * 8];
            *(float4*)(a + 4) = *(const float4*)&As[kk][ty * 8 + 4];
            *(float4*)(bb)     = *(const float4*)&Bs[kk][tx * 8];
            *(float4*)(bb + 4) = *(const float4*)&Bs[kk][tx * 8 + 4];
#pragma unroll
            for (int i = 0; i < 8; i++)
#pragma unroll
                for (int j = 0; j < 8; j++) acc[i][j] += a[i] * bb[j];
        }
        __syncthreads();
    }
#pragma unroll
    for (int i = 0; i < 8; i++) {
        size_t idx = (size_t)(m0 + ty * 8 + i) * HW + n0 + tx * 8;
        *(float4*)&O[idx]     = *(float4*)&acc[i][0];
        *(float4*)&O[idx + 4] = *(float4*)&acc[i][4];
    }
}

// ======== Proj + residual: out = x + Wp*g_ao + bp  (NN form) ===============
__global__ void __launch_bounds__(256) proj_kernel(const float* __restrict__ Wp,
                                                   const float* __restrict__ bp,
                                                   const float* __restrict__ x,
                                                   float* __restrict__ out) {
    int m0 = blockIdx.y * 128;
    int n0 = blockIdx.x * 128;
    int b  = blockIdx.z;
    const float* X = g_ao + (size_t)b * CH * HW;

    __shared__ float As[8][128];
    __shared__ float Bs[8][128];
    float acc[8][8];
#pragma unroll
    for (int i = 0; i < 8; i++)
#pragma unroll
        for (int j = 0; j < 8; j++) acc[i][j] = 0.f;

    int t = threadIdx.x, tx = t & 15, ty = t >> 4;
    int ar = t >> 1, ac = (t & 1) * 4;
    int br = t >> 5, bc = (t & 31) * 4;

    for (int k0 = 0; k0 < CH; k0 += 8) {
        float4 av = *(const float4*)&Wp[(m0 + ar) * CH + k0 + ac];
        As[ac + 0][ar] = av.x; As[ac + 1][ar] = av.y;
        As[ac + 2][ar] = av.z; As[ac + 3][ar] = av.w;
        *(float4*)&Bs[br][bc] = *(const float4*)&X[(size_t)(k0 + br) * HW + n0 + bc];
        __syncthreads();
#pragma unroll
        for (int kk = 0; kk < 8; kk++) {
            float a[8], bb[8];
            *(float4*)(a)     = *(const float4*)&As[kk][ty * 8];
            *(float4*)(a + 4) = *(const float4*)&As[kk][ty * 8 + 4];
            *(float4*)(bb)     = *(const float4*)&Bs[kk][tx * 8];
            *(float4*)(bb + 4) = *(const float4*)&Bs[kk][tx * 8 + 4];
#pragma unroll
            for (int i = 0; i < 8; i++)
#pragma unroll
                for (int j = 0; j < 8; j++) acc[i][j] += a[i] * bb[j];
        }
        __syncthreads();
    }
#pragma unroll
    for (int i = 0; i < 8; i++) {
        int row = m0 + ty * 8 + i;
        float bv = bp[row];
        size_t idx = ((size_t)b * CH + row) * HW + n0 + tx * 8;
        float4 r0 = *(const float4*)&x[idx];
        float4 r1 = *(const float4*)&x[idx + 4];
        float4 o0 = {acc[i][0] + bv + r0.x, acc[i][1] + bv + r0.y,
                     acc[i][2] + bv + r0.z, acc[i][3] + bv + r0.w};
        float4 o1 = {acc[i][4] + bv + r1.x, acc[i][5] + bv + r1.y,
                     acc[i][6] + bv + r1.z, acc[i][7] + bv + r1.w};
        *(float4*)&out[idx]     = o0;
        *(float4*)&out[idx + 4] = o1;
    }
}

// ============================== launch ======================================
extern "C" void kernel_launch(void* const* d_in, const int* in_sizes, int n_in,
                              void* d_out, int out_size) {
    const float* x    = (const float*)d_in[0];
    const float* gns  = (const float*)d_in[1];
    const float* gnb  = (const float*)d_in[2];
    const float* wq   = (const float*)d_in[3];
    const float* bq   = (const float*)d_in[4];
    const float* wk   = (const float*)d_in[5];
    const float* bk   = (const float*)d_in[6];
    const float* wv   = (const float*)d_in[7];
    const float* bv   = (const float*)d_in[8];
    const float* wp   = (const float*)d_in[9];
    const float* bp   = (const float*)d_in[10];
    float* out = (float*)d_out;

    gn_kernel<<<BSZ * GRP, 256>>>(x, gns, gnb);
    qkv_kernel<<<dim3(HW / 128, 6, BSZ), 256>>>(wq, bq, wk, bk, wv, bv);
    scores_kernel<<<dim3(HW / 128, HW / 128, BSZ), 256>>>();
    softmax_kernel<<<BSZ * HW, 256>>>();
    pv_kernel<<<dim3(HW / 128, CH / 128, BSZ), 256>>>();
    proj_kernel<<<dim3(HW / 128, CH / 128, BSZ), 256>>>(wp, bp, x, out);
}

// round 3
// speedup vs baseline: 3.3070x; 3.3070x over previous
#include <cuda_runtime.h>
#include <cuda_bf16.h>
#include <math.h>
#include <stdint.h>

// Shapes (fixed by the problem)
#define BSZ 8
#define CH  256
#define HW  4096            // 64*64 tokens
#define GRP 32
#define CPG 8               // channels per group

// ---------------- scratch (static device globals; no runtime alloc) --------
__device__ float g_hn[BSZ * CH * HW];                           // 32 MB fp32
__device__ __nv_bfloat16 g_qT[(size_t)BSZ * HW * CH];           // q^T [b][n][c]
__device__ __nv_bfloat16 g_kT[(size_t)BSZ * HW * CH];           // k^T [b][m][c]
__device__ __nv_bfloat16 g_vh[(size_t)BSZ * CH * HW];           // v   [b][c][m]
__device__ float         g_s [(size_t)BSZ * HW * HW];           // scores fp32 512MB
__device__ __nv_bfloat16 g_p [(size_t)BSZ * HW * HW];           // probs bf16 256MB
__device__ float         g_ao[BSZ * CH * HW];                   // attn out fp32

// ====================== PTX helpers (sm_80+ features only) ==================
__device__ __forceinline__ uint32_t smem_u32(const void* p) {
    uint32_t a;
    asm("{ .reg .u64 t; cvta.to.shared.u64 t, %1; cvt.u32.u64 %0, t; }" : "=r"(a) : "l"(p));
    return a;
}
__device__ __forceinline__ void ldsm_x4(uint32_t* r, uint32_t addr) {
    asm volatile("ldmatrix.sync.aligned.m8n8.x4.shared.b16 {%0,%1,%2,%3}, [%4];"
        : "=r"(r[0]), "=r"(r[1]), "=r"(r[2]), "=r"(r[3]) : "r"(addr));
}
__device__ __forceinline__ void mma_bf16(float* d, const uint32_t* a, const uint32_t* b) {
    asm volatile("mma.sync.aligned.m16n8k16.row.col.f32.bf16.bf16.f32 "
        "{%0,%1,%2,%3}, {%4,%5,%6,%7}, {%8,%9}, {%0,%1,%2,%3};"
        : "+f"(d[0]), "+f"(d[1]), "+f"(d[2]), "+f"(d[3])
        : "r"(a[0]), "r"(a[1]), "r"(a[2]), "r"(a[3]), "r"(b[0]), "r"(b[1]));
}
#define CP_ASYNC16(s, g) asm volatile("cp.async.cg.shared.global [%0], [%1], 16;" :: "r"(s), "l"(g))
#define CP_COMMIT()      asm volatile("cp.async.commit_group;" ::: "memory")
#define CP_WAIT1()       asm volatile("cp.async.wait_group 1;" ::: "memory")
#define CP_WAIT0()       asm volatile("cp.async.wait_group 0;" ::: "memory")

// smem tile geometry: 128 rows x 32 bf16 (64B data), padded row stride 80B
static constexpr int ROW_B   = 80;
static constexpr int TILE_B  = 128 * ROW_B;    // 10240
static constexpr int BUF_B   = 2 * TILE_B;     // A + B per stage = 20480
// double buffered: 40960 bytes static smem

// Fill one 128x32 bf16 K-major tile stage via cp.async (g pre-offset to k0).
__device__ __forceinline__ void fill_tile(const __nv_bfloat16* __restrict__ g,
                                          size_t stride, uint32_t sbase, int t) {
#pragma unroll
    for (int it = 0; it < 2; it++) {
        int chunk = t + it * 256;           // 512 chunks of 16B
        int row = chunk >> 2, c16 = chunk & 3;
        const void* gp = g + (size_t)row * stride + c16 * 8;
        uint32_t sp = sbase + row * ROW_B + c16 * 16;
        CP_ASYNC16(sp, gp);
    }
}

// ============ HMMA GEMM: D[128][128] = A(K-major) @ B(K-major)^T ============
// MODE 0: scores  D[n][m] = qT[n][c] * kT[m][c],  K=256,  scale 1/16
// MODE 1: PV      D[c][n] = v[c][m]  * P[n][m],   K=4096, scale 1
template <int MODE>
__global__ void __launch_bounds__(256) gemm_mma() {
    const int K = (MODE == 0) ? CH : HW;
    const size_t stride = (size_t)K;        // both operands: row stride == K
    int n0 = blockIdx.x * 128, m0 = blockIdx.y * 128, z = blockIdx.z;

    const __nv_bfloat16* A;
    const __nv_bfloat16* B;
    float* D;
    if (MODE == 0) {
        A = g_qT + (size_t)z * HW * CH + (size_t)m0 * stride;
        B = g_kT + (size_t)z * HW * CH + (size_t)n0 * stride;
        D = g_s  + (size_t)z * HW * HW;
    } else {
        A = g_vh + (size_t)z * CH * HW + (size_t)m0 * stride;
        B = g_p  + (size_t)z * HW * HW + (size_t)n0 * stride;
        D = g_ao + (size_t)z * CH * HW;
    }

    __shared__ __align__(16) char smem[2 * BUF_B];
    uint32_t sb = smem_u32(smem);
    int t = threadIdx.x, wid = t >> 5, lane = t & 31;
    int wm = wid >> 2, wn = wid & 3;        // warp grid 2(m) x 4(n)

    float acc[4][4][4];
#pragma unroll
    for (int i = 0; i < 4; i++)
#pragma unroll
        for (int j = 0; j < 4; j++)
#pragma unroll
            for (int r = 0; r < 4; r++) acc[i][j][r] = 0.f;

    const int NC = K / 32;
    // prologue: stage 0
    fill_tile(A, stride, sb, t);
    fill_tile(B, stride, sb + TILE_B, t);
    CP_COMMIT();

#pragma unroll 1
    for (int c = 0; c < NC; c++) {
        int buf = c & 1;
        if (c + 1 < NC) {
            uint32_t nb = sb + ((c + 1) & 1) * BUF_B;
            fill_tile(A + (c + 1) * 32, stride, nb, t);
            fill_tile(B + (c + 1) * 32, stride, nb + TILE_B, t);
            CP_COMMIT();
            CP_WAIT1();
        } else {
            CP_WAIT0();
        }
        __syncthreads();

        uint32_t ab = sb + buf * BUF_B;
        uint32_t bb = ab + TILE_B;
#pragma unroll
        for (int ks = 0; ks < 2; ks++) {
            uint32_t a_frag[4][4];
            uint32_t b_frag[4][2];
#pragma unroll
            for (int mt = 0; mt < 4; mt++) {
                int row = wm * 64 + mt * 16 + (lane & 15);
                uint32_t addr = ab + row * ROW_B + (ks * 16 + (lane >> 4) * 8) * 2;
                ldsm_x4(a_frag[mt], addr);
            }
#pragma unroll
            for (int p = 0; p < 2; p++) {
                int row = wn * 32 + p * 16 + (lane & 15);
                uint32_t addr = bb + row * ROW_B + (ks * 16 + (lane >> 4) * 8) * 2;
                uint32_t q[4];
                ldsm_x4(q, addr);
                b_frag[2 * p][0]     = q[0]; b_frag[2 * p][1]     = q[2];
                b_frag[2 * p + 1][0] = q[1]; b_frag[2 * p + 1][1] = q[3];
            }
#pragma unroll
            for (int mt = 0; mt < 4; mt++)
#pragma unroll
                for (int nt = 0; nt < 4; nt++)
                    mma_bf16(acc[mt][nt], a_frag[mt], b_frag[nt]);
        }
        __syncthreads();
    }

    // epilogue: d0 (r,c) d1 (r,c+1) d2 (r+8,c) d3 (r+8,c+1)
    const float scale = (MODE == 0) ? 0.0625f : 1.0f;
    int r0 = m0 + wm * 64 + (lane >> 2);
    int c0 = n0 + wn * 32 + (lane & 3) * 2;
#pragma unroll
    for (int mt = 0; mt < 4; mt++) {
#pragma unroll
        for (int nt = 0; nt < 4; nt++) {
            size_t base = (size_t)(r0 + mt * 16) * HW + c0 + nt * 8;
            float2 v0 = {acc[mt][nt][0] * scale, acc[mt][nt][1] * scale};
            float2 v1 = {acc[mt][nt][2] * scale, acc[mt][nt][3] * scale};
            *(float2*)&D[base]            = v0;
            *(float2*)&D[base + 8 * HW]   = v1;
        }
    }
}

// ============================ GroupNorm =====================================
__global__ void __launch_bounds__(256) gn_kernel(const float* __restrict__ x,
                                                 const float* __restrict__ sc,
                                                 const float* __restrict__ bi) {
    int b = blockIdx.x >> 5;
    int g = blockIdx.x & 31;
    const float* xp = x    + ((size_t)b * CH + g * CPG) * HW;
    float*       op = g_hn + ((size_t)b * CH + g * CPG) * HW;
    int t = threadIdx.x;
    const int TOT = CPG * HW;

    float s = 0.f, s2 = 0.f;
    for (int i = t * 4; i < TOT; i += 1024) {
        float4 v = *(const float4*)&xp[i];
        s  += v.x + v.y + v.z + v.w;
        s2 += v.x * v.x + v.y * v.y + v.z * v.z + v.w * v.w;
    }
    __shared__ float rs[256], rs2[256];
    rs[t] = s; rs2[t] = s2;
    __syncthreads();
    for (int o = 128; o > 0; o >>= 1) {
        if (t < o) { rs[t] += rs[t + o]; rs2[t] += rs2[t + o]; }
        __syncthreads();
    }
    float mean = rs[0] * (1.0f / TOT);
    float var  = rs2[0] * (1.0f / TOT) - mean * mean;
    float inv  = rsqrtf(var + 1e-6f);

    for (int i = t * 4; i < TOT; i += 1024) {
        int c = g * CPG + (i >> 12);
        float a  = sc[c] * inv;
        float bb = bi[c] - mean * a;
        float4 v = *(const float4*)&xp[i];
        float4 o;
        o.x = v.x * a + bb; o.y = v.y * a + bb;
        o.z = v.z * a + bb; o.w = v.w * a + bb;
        *(float4*)&op[i] = o;
    }
}

// ===================== QKV GEMM -> bf16 q^T, k^T, v ========================
__global__ void __launch_bounds__(256) qkv_kernel(const float* __restrict__ wq,
                                                  const float* __restrict__ bq,
                                                  const float* __restrict__ wk,
                                                  const float* __restrict__ bk,
                                                  const float* __restrict__ wv,
                                                  const float* __restrict__ bv) {
    int which = blockIdx.y >> 1;
    int m0 = (blockIdx.y & 1) * 128;
    int n0 = blockIdx.x * 128;
    int b  = blockIdx.z;
    const float* W    = (which == 0) ? wq : (which == 1) ? wk : wv;
    const float* bias = (which == 0) ? bq : (which == 1) ? bk : bv;
    const float* X    = g_hn + (size_t)b * CH * HW;

    __shared__ float As[8][128];
    __shared__ float Bs[8][128];
    float acc[8][8];
#pragma unroll
    for (int i = 0; i < 8; i++)
#pragma unroll
        for (int j = 0; j < 8; j++) acc[i][j] = 0.f;

    int t = threadIdx.x, tx = t & 15, ty = t >> 4;
    int ar = t >> 1, ac = (t & 1) * 4;
    int br = t >> 5, bc = (t & 31) * 4;

    for (int k0 = 0; k0 < CH; k0 += 8) {
        float4 av = *(const float4*)&W[(m0 + ar) * CH + k0 + ac];
        As[ac + 0][ar] = av.x; As[ac + 1][ar] = av.y;
        As[ac + 2][ar] = av.z; As[ac + 3][ar] = av.w;
        *(float4*)&Bs[br][bc] = *(const float4*)&X[(size_t)(k0 + br) * HW + n0 + bc];
        __syncthreads();
#pragma unroll
        for (int kk = 0; kk < 8; kk++) {
            float a[8], bb[8];
            *(float4*)(a)     = *(const float4*)&As[kk][ty * 8];
            *(float4*)(a + 4) = *(const float4*)&As[kk][ty * 8 + 4];
            *(float4*)(bb)     = *(const float4*)&Bs[kk][tx * 8];
            *(float4*)(bb + 4) = *(const float4*)&Bs[kk][tx * 8 + 4];
#pragma unroll
            for (int i = 0; i < 8; i++)
#pragma unroll
                for (int j = 0; j < 8; j++) acc[i][j] += a[i] * bb[j];
        }
        __syncthreads();
    }
    if (which == 2) {
        // v: [b][c][m] bf16, rows contiguous in tokens
        __nv_bfloat16* out = g_vh + (size_t)b * CH * HW;
#pragma unroll
        for (int i = 0; i < 8; i++) {
            int row = m0 + ty * 8 + i;
            float bv2 = bias[row];
            __nv_bfloat162 p[4];
#pragma unroll
            for (int j = 0; j < 4; j++)
                p[j] = __float22bfloat162_rn(make_float2(acc[i][2 * j] + bv2,
                                                         acc[i][2 * j + 1] + bv2));
            *(uint4*)&out[(size_t)row * HW + n0 + tx * 8] = *(uint4*)p;
        }
    } else {
        // q^T / k^T: [b][n][c] bf16 (scattered 2B stores)
        __nv_bfloat16* out = ((which == 0) ? g_qT : g_kT) + (size_t)b * HW * CH;
#pragma unroll
        for (int i = 0; i < 8; i++) {
            int row = m0 + ty * 8 + i;   // channel
            float bv2 = bias[row];
#pragma unroll
            for (int j = 0; j < 8; j++) {
                int col = n0 + tx * 8 + j;   // token
                out[(size_t)col * CH + row] = __float2bfloat16(acc[i][j] + bv2);
            }
        }
    }
}

// ============== Row softmax over m: reads fp32 S, writes bf16 P =============
__global__ void __launch_bounds__(256) softmax_kernel() {
    size_t row = blockIdx.x;                 // b*4096 + n
    const float* p = g_s + row * (size_t)HW;
    __nv_bfloat16* q = g_p + row * (size_t)HW;
    int t = threadIdx.x;

    float4 v[4];
    float mx = -1e30f;
#pragma unroll
    for (int i = 0; i < 4; i++) {
        v[i] = *(const float4*)&p[t * 4 + i * 1024];
        mx = fmaxf(mx, fmaxf(fmaxf(v[i].x, v[i].y), fmaxf(v[i].z, v[i].w)));
    }
    __shared__ float red[256];
    red[t] = mx; __syncthreads();
    for (int o = 128; o > 0; o >>= 1) {
        if (t < o) red[t] = fmaxf(red[t], red[t + o]);
        __syncthreads();
    }
    mx = red[0];
    __syncthreads();

    float sum = 0.f;
#pragma unroll
    for (int i = 0; i < 4; i++) {
        v[i].x = __expf(v[i].x - mx); v[i].y = __expf(v[i].y - mx);
        v[i].z = __expf(v[i].z - mx); v[i].w = __expf(v[i].w - mx);
        sum += v[i].x + v[i].y + v[i].z + v[i].w;
    }
    red[t] = sum; __syncthreads();
    for (int o = 128; o > 0; o >>= 1) {
        if (t < o) red[t] += red[t + o];
        __syncthreads();
    }
    float inv = 1.0f / red[0];
#pragma unroll
    for (int i = 0; i < 4; i++) {
        __nv_bfloat162 o0 = __float22bfloat162_rn(make_float2(v[i].x * inv, v[i].y * inv));
        __nv_bfloat162 o1 = __float22bfloat162_rn(make_float2(v[i].z * inv, v[i].w * inv));
        uint2 pk = {*(uint32_t*)&o0, *(uint32_t*)&o1};
        *(uint2*)&q[t * 4 + i * 1024] = pk;
    }
}

// ======== Proj + residual: out = x + Wp*g_ao + bp  (NN form, fp32) =========
__global__ void __launch_bounds__(256) proj_kernel(const float* __restrict__ Wp,
                                                   const float* __restrict__ bp,
                                                   const float* __restrict__ x,
                                                   float* __restrict__ out) {
    int m0 = blockIdx.y * 128;
    int n0 = blockIdx.x * 128;
    int b  = blockIdx.z;
    const float* X = g_ao + (size_t)b * CH * HW;

    __shared__ float As[8][128];
    __shared__ float Bs[8][128];
    float acc[8][8];
#pragma unroll
    for (int i = 0; i < 8; i++)
#pragma unroll
        for (int j = 0; j < 8; j++) acc[i][j] = 0.f;

    int t = threadIdx.x, tx = t & 15, ty = t >> 4;
    int ar = t >> 1, ac = (t & 1) * 4;
    int br = t >> 5, bc = (t & 31) * 4;

    for (int k0 = 0; k0 < CH; k0 += 8) {
        float4 av = *(const float4*)&Wp[(m0 + ar) * CH + k0 + ac];
        As[ac + 0][ar] = av.x; As[ac + 1][ar] = av.y;
        As[ac + 2][ar] = av.z; As[ac + 3][ar] = av.w;
        *(float4*)&Bs[br][bc] = *(const float4*)&X[(size_t)(k0 + br) * HW + n0 + bc];
        __syncthreads();
#pragma unroll
        for (int kk = 0; kk < 8; kk++) {
            float a[8], bb[8];
            *(float4*)(a)     = *(const float4*)&As[kk][ty * 8];
            *(float4*)(a + 4) = *(const float4*)&As[kk][ty * 8 + 4];
            *(float4*)(bb)     = *(const float4*)&Bs[kk][tx * 8];
            *(float4*)(bb + 4) = *(const float4*)&Bs[kk][tx * 8 + 4];
#pragma unroll
            for (int i = 0; i < 8; i++)
#pragma unroll
                for (int j = 0; j < 8; j++) acc[i][j] += a[i] * bb[j];
        }
        __syncthreads();
    }
#pragma unroll
    for (int i = 0; i < 8; i++) {
        int row = m0 + ty * 8 + i;
        float bv = bp[row];
        size_t idx = ((size_t)b * CH + row) * HW + n0 + tx * 8;
        float4 r0 = *(const float4*)&x[idx];
        float4 r1 = *(const float4*)&x[idx + 4];
        float4 o0 = {acc[i][0] + bv + r0.x, acc[i][1] + bv + r0.y,
                     acc[i][2] + bv + r0.z, acc[i][3] + bv + r0.w};
        float4 o1 = {acc[i][4] + bv + r1.x, acc[i][5] + bv + r1.y,
                     acc[i][6] + bv + r1.z, acc[i][7] + bv + r1.w};
        *(float4*)&out[idx]     = o0;
        *(float4*)&out[idx + 4] = o1;
    }
}

// ============================== launch ======================================
extern "C" void kernel_launch(void* const* d_in, const int* in_sizes, int n_in,
                              void* d_out, int out_size) {
    const float* x    = (const float*)d_in[0];
    const float* gns  = (const float*)d_in[1];
    const float* gnb  = (const float*)d_in[2];
    const float* wq   = (const float*)d_in[3];
    const float* bq   = (const float*)d_in[4];
    const float* wk   = (const float*)d_in[5];
    const float* bk   = (const float*)d_in[6];
    const float* wv   = (const float*)d_in[7];
    const float* bv   = (const float*)d_in[8];
    const float* wp   = (const float*)d_in[9];
    const float* bp   = (const float*)d_in[10];
    float* out = (float*)d_out;

    gn_kernel<<<BSZ * GRP, 256>>>(x, gns, gnb);
    qkv_kernel<<<dim3(HW / 128, 6, BSZ), 256>>>(wq, bq, wk, bk, wv, bv);
    // scores: S[n][m] = qT[n][:] . kT[m][:] / 16
    gemm_mma<0><<<dim3(HW / 128, HW / 128, BSZ), 256>>>();
    softmax_kernel<<<BSZ * HW, 256>>>();
    // PV: ao[c][n] = v[c][:] . P[n][:]
    gemm_mma<1><<<dim3(HW / 128, CH / 128, BSZ), 256>>>();
    proj_kernel<<<dim3(HW / 128, CH / 128, BSZ), 256>>>(wp, bp, x, out);
}

// round 5
// speedup vs baseline: 5.0014x; 1.5124x over previous
#include <cuda_runtime.h>
#include <cuda_bf16.h>
#include <math.h>
#include <stdint.h>

// Shapes (fixed by the problem)
#define BSZ 8
#define CH  256
#define HW  4096            // 64*64 tokens
#define CPG 8               // channels per group

// ---------------- scratch (static device globals; no runtime alloc) --------
__device__ __nv_bfloat16 g_hnb[(size_t)BSZ * CH * HW];          // groupnormed x, [b][c][n]
__device__ __nv_bfloat16 g_q2[(size_t)BSZ * CH * HW];           // q [b][c][n]
__device__ __nv_bfloat16 g_k2[(size_t)BSZ * CH * HW];           // k [b][c][n]
__device__ __nv_bfloat16 g_v2[(size_t)BSZ * CH * HW];           // v [b][c][n]
__device__ __nv_bfloat16 g_aob[(size_t)BSZ * CH * HW];          // attn out [b][c][n]
__device__ float         g_s [(size_t)BSZ * HW * HW];           // scores fp32 512MB
__device__ __nv_bfloat16 g_p [(size_t)BSZ * HW * HW];           // probs bf16 256MB
__device__ __nv_bfloat16 g_wb[3 * CH * CH];                     // wq,wk,wv bf16
__device__ __nv_bfloat16 g_wpb[CH * CH];                        // wproj bf16

// ====================== PTX helpers (sm_80+ features only) ==================
__device__ __forceinline__ uint32_t smem_u32(const void* p) {
    uint32_t a;
    asm("{ .reg .u64 t; cvta.to.shared.u64 t, %1; cvt.u32.u64 %0, t; }" : "=r"(a) : "l"(p));
    return a;
}
__device__ __forceinline__ void ldsm_x4(uint32_t* r, uint32_t addr) {
    asm volatile("ldmatrix.sync.aligned.m8n8.x4.shared.b16 {%0,%1,%2,%3}, [%4];"
        : "=r"(r[0]), "=r"(r[1]), "=r"(r[2]), "=r"(r[3]) : "r"(addr));
}
__device__ __forceinline__ void ldsm_x4_t(uint32_t* r, uint32_t addr) {
    asm volatile("ldmatrix.sync.aligned.m8n8.x4.trans.shared.b16 {%0,%1,%2,%3}, [%4];"
        : "=r"(r[0]), "=r"(r[1]), "=r"(r[2]), "=r"(r[3]) : "r"(addr));
}
__device__ __forceinline__ void mma_bf16(float* d, const uint32_t* a, const uint32_t* b) {
    asm volatile("mma.sync.aligned.m16n8k16.row.col.f32.bf16.bf16.f32 "
        "{%0,%1,%2,%3}, {%4,%5,%6,%7}, {%8,%9}, {%0,%1,%2,%3};"
        : "+f"(d[0]), "+f"(d[1]), "+f"(d[2]), "+f"(d[3])
        : "r"(a[0]), "r"(a[1]), "r"(a[2]), "r"(a[3]), "r"(b[0]), "r"(b[1]));
}
#define CP_ASYNC16(s, g) asm volatile("cp.async.cg.shared.global [%0], [%1], 16;" :: "r"(s), "l"(g))
#define CP_COMMIT()      asm volatile("cp.async.commit_group;" ::: "memory")
#define CP_WAIT1()       asm volatile("cp.async.wait_group 1;" ::: "memory")
#define CP_WAIT0()       asm volatile("cp.async.wait_group 0;" ::: "memory")

// Tile geometry.
// Normal (K-major [m][k]):  128 rows x 32 bf16, padded row stride 80B.
// Trans  ([k][m]):          32 k-rows x 128 bf16 (256B), padded stride 272B.
static constexpr int ROW_N  = 80;
static constexpr int ROW_T  = 272;
static constexpr int TILE_N = 128 * ROW_N;   // 10240
static constexpr int TILE_T = 32 * ROW_T;    // 8704

template <bool TR>
__device__ __forceinline__ void fill_tile(const __nv_bfloat16* __restrict__ g,
                                          size_t stride, uint32_t sbase, int t) {
#pragma unroll
    for (int it = 0; it < 2; it++) {
        int chunk = t + it * 256;           // 512 chunks of 16B
        if (TR) {
            int row = chunk >> 4, c16 = chunk & 15;
            CP_ASYNC16(sbase + row * ROW_T + c16 * 16,
                       g + (size_t)row * stride + c16 * 8);
        } else {
            int row = chunk >> 2, c16 = chunk & 3;
            CP_ASYNC16(sbase + row * ROW_N + c16 * 16,
                       g + (size_t)row * stride + c16 * 8);
        }
    }
}

// ===================== Unified HMMA GEMM ====================================
// Computes D[128][128] tile = A x B^T over K, CTA tile 128x128, warps 2x4.
// MODE 0: QKV   q/k/v[c][n] = W[o][c] * hn[c][n] + bias      (A normal, B trans)
// MODE 1: scores S[n][m] = (1/16) q[c][n]^T k[c][m]          (A trans,  B trans)
// MODE 2: PV    ao[c][n] = v[c][m] * P[n][m]                 (A normal, B normal)
// MODE 3: proj  out = x + Wp[o][c] * ao[c][n] + bias         (A normal, B trans)
template <int MODE>
__global__ void __launch_bounds__(256) gemm_bf16(const float* __restrict__ bias0,
                                                 const float* __restrict__ bias1,
                                                 const float* __restrict__ bias2,
                                                 const float* __restrict__ xres,
                                                 float* __restrict__ outp) {
    constexpr bool AT = (MODE == 1);
    constexpr bool BT = (MODE != 2);
    constexpr int  K  = (MODE == 2) ? HW : CH;
    constexpr int  NC = K / 32;
    constexpr int  ATILE = AT ? TILE_T : TILE_N;
    constexpr int  BTILE = BT ? TILE_T : TILE_N;
    constexpr int  STAGE = ATILE + BTILE;

    int n0 = blockIdx.x * 128, z = blockIdx.z;
    int which = 0, m0;
    if (MODE == 0) { which = blockIdx.y >> 1; m0 = (blockIdx.y & 1) * 128; }
    else           { m0 = blockIdx.y * 128; }

    const __nv_bfloat16 *A, *B;
    size_t astride, bstride;
    if (MODE == 0) {
        A = g_wb + (size_t)which * CH * CH + (size_t)m0 * CH;  astride = CH;
        B = g_hnb + (size_t)z * CH * HW + n0;                  bstride = HW;
    } else if (MODE == 1) {
        A = g_q2 + (size_t)z * CH * HW + m0;                   astride = HW;
        B = g_k2 + (size_t)z * CH * HW + n0;                   bstride = HW;
    } else if (MODE == 2) {
        A = g_v2 + (size_t)z * CH * HW + (size_t)m0 * HW;      astride = HW;
        B = g_p  + (size_t)z * HW * HW + (size_t)n0 * HW;      bstride = HW;
    } else {
        A = g_wpb + (size_t)m0 * CH;                           astride = CH;
        B = g_aob + (size_t)z * CH * HW + n0;                  bstride = HW;
    }
    // per-chunk advance: normal moves along columns (k), trans moves down k-rows
    auto a_off = [&](int c) -> size_t { return AT ? (size_t)c * 32 * astride : (size_t)c * 32; };
    auto b_off = [&](int c) -> size_t { return BT ? (size_t)c * 32 * bstride : (size_t)c * 32; };

    __shared__ __align__(16) char smem[2 * STAGE];
    uint32_t sb = smem_u32(smem);
    int t = threadIdx.x, wid = t >> 5, lane = t & 31;
    int wm = wid >> 2, wn = wid & 3;

    float acc[4][4][4];
#pragma unroll
    for (int i = 0; i < 4; i++)
#pragma unroll
        for (int j = 0; j < 4; j++)
#pragma unroll
            for (int r = 0; r < 4; r++) acc[i][j][r] = 0.f;

    fill_tile<AT>(A, astride, sb, t);
    fill_tile<BT>(B, bstride, sb + ATILE, t);
    CP_COMMIT();

#pragma unroll 1
    for (int c = 0; c < NC; c++) {
        int buf = c & 1;
        if (c + 1 < NC) {
            uint32_t nb = sb + ((c + 1) & 1) * STAGE;
            fill_tile<AT>(A + a_off(c + 1), astride, nb, t);
            fill_tile<BT>(B + b_off(c + 1), bstride, nb + ATILE, t);
            CP_COMMIT();
            CP_WAIT1();
        } else {
            CP_WAIT0();
        }
        __syncthreads();

        uint32_t ab = sb + buf * STAGE;
        uint32_t bb = ab + ATILE;
#pragma unroll
        for (int ks = 0; ks < 2; ks++) {
            uint32_t a_frag[4][4];
            uint32_t b_frag[4][2];
#pragma unroll
            for (int mt = 0; mt < 4; mt++) {
                if (AT) {
                    int krow = (lane & 7) + ((lane >> 4) << 3) + ks * 16;
                    int mcol = wm * 64 + mt * 16 + ((lane >> 3) & 1) * 8;
                    ldsm_x4_t(a_frag[mt], ab + krow * ROW_T + mcol * 2);
                } else {
                    int row = wm * 64 + mt * 16 + (lane & 15);
                    ldsm_x4(a_frag[mt], ab + row * ROW_N + (ks * 16 + (lane >> 4) * 8) * 2);
                }
            }
#pragma unroll
            for (int p = 0; p < 2; p++) {
                uint32_t q[4];
                if (BT) {
                    int krow = (lane & 7) + ((lane >> 4) << 3) + ks * 16;
                    int ncol = wn * 32 + p * 16 + ((lane >> 3) & 1) * 8;
                    ldsm_x4_t(q, bb + krow * ROW_T + ncol * 2);
                } else {
                    int row = wn * 32 + p * 16 + (lane & 15);
                    ldsm_x4(q, bb + row * ROW_N + (ks * 16 + (lane >> 4) * 8) * 2);
                }
                b_frag[2 * p][0]     = q[0]; b_frag[2 * p][1]     = q[2];
                b_frag[2 * p + 1][0] = q[1]; b_frag[2 * p + 1][1] = q[3];
            }
#pragma unroll
            for (int mt = 0; mt < 4; mt++)
#pragma unroll
                for (int nt = 0; nt < 4; nt++)
                    mma_bf16(acc[mt][nt], a_frag[mt], b_frag[nt]);
        }
        __syncthreads();
    }

    // epilogue: d0 (r,c) d1 (r,c+1) d2 (r+8,c) d3 (r+8,c+1)
    int r0 = m0 + wm * 64 + (lane >> 2);
    int c0 = n0 + wn * 32 + (lane & 3) * 2;

    if (MODE == 1) {
        float* D = g_s + (size_t)z * HW * HW;
#pragma unroll
        for (int mt = 0; mt < 4; mt++)
#pragma unroll
            for (int nt = 0; nt < 4; nt++) {
                size_t base = (size_t)(r0 + mt * 16) * HW + c0 + nt * 8;
                float2 v0 = {acc[mt][nt][0] * 0.0625f, acc[mt][nt][1] * 0.0625f};
                float2 v1 = {acc[mt][nt][2] * 0.0625f, acc[mt][nt][3] * 0.0625f};
                *(float2*)&D[base]          = v0;
                *(float2*)&D[base + 8 * HW] = v1;
            }
    } else if (MODE == 0 || MODE == 2) {
        __nv_bfloat16* D;
        const float* bias = nullptr;
        if (MODE == 0) {
            D = ((which == 0) ? g_q2 : (which == 1) ? g_k2 : g_v2) + (size_t)z * CH * HW;
            bias = (which == 0) ? bias0 : (which == 1) ? bias1 : bias2;
        } else {
            D = g_aob + (size_t)z * CH * HW;
        }
#pragma unroll
        for (int mt = 0; mt < 4; mt++) {
            int r = r0 + mt * 16;
            float b1 = (MODE == 0) ? bias[r] : 0.f;
            float b2 = (MODE == 0) ? bias[r + 8] : 0.f;
#pragma unroll
            for (int nt = 0; nt < 4; nt++) {
                size_t base = (size_t)r * HW + c0 + nt * 8;
                __nv_bfloat162 o0 = __float22bfloat162_rn(
                    make_float2(acc[mt][nt][0] + b1, acc[mt][nt][1] + b1));
                __nv_bfloat162 o1 = __float22bfloat162_rn(
                    make_float2(acc[mt][nt][2] + b2, acc[mt][nt][3] + b2));
                *(__nv_bfloat162*)&D[base]          = o0;
                *(__nv_bfloat162*)&D[base + 8 * HW] = o1;
            }
        }
    } else {  // MODE 3: proj + bias + residual, fp32 out
#pragma unroll
        for (int mt = 0; mt < 4; mt++) {
            int r = r0 + mt * 16;
            float b1 = bias0[r], b2 = bias0[r + 8];
#pragma unroll
            for (int nt = 0; nt < 4; nt++) {
                size_t idx = ((size_t)z * CH + r) * HW + c0 + nt * 8;
                float2 x0 = *(const float2*)&xres[idx];
                float2 x1 = *(const float2*)&xres[idx + 8 * HW];
                float2 v0 = {acc[mt][nt][0] + b1 + x0.x, acc[mt][nt][1] + b1 + x0.y};
                float2 v1 = {acc[mt][nt][2] + b2 + x1.x, acc[mt][nt][3] + b2 + x1.y};
                *(float2*)&outp[idx]          = v0;
                *(float2*)&outp[idx + 8 * HW] = v1;
            }
        }
    }
}

// ================= weights fp32 -> bf16 (tiny, once per call) ===============
__global__ void __launch_bounds__(256) wconv_kernel(const float* __restrict__ wq,
                                                    const float* __restrict__ wk,
                                                    const float* __restrict__ wv,
                                                    const float* __restrict__ wp) {
    int i = blockIdx.x * 256 + threadIdx.x;      // 16384 float4s per matrix
    const float* srcs[4] = {wq, wk, wv, wp};
    __nv_bfloat16* dsts[4] = {g_wb, g_wb + CH * CH, g_wb + 2 * CH * CH, g_wpb};
#pragma unroll
    for (int m = 0; m < 4; m++) {
        float4 a = ((const float4*)srcs[m])[i];
        __nv_bfloat162 p0 = __float22bfloat162_rn(make_float2(a.x, a.y));
        __nv_bfloat162 p1 = __float22bfloat162_rn(make_float2(a.z, a.w));
        uint2 pk = {*(uint32_t*)&p0, *(uint32_t*)&p1};
        *(uint2*)&dsts[m][i * 4] = pk;
    }
}

// ============================ GroupNorm -> bf16 =============================
__global__ void __launch_bounds__(256) gn_kernel(const float* __restrict__ x,
                                                 const float* __restrict__ sc,
                                                 const float* __restrict__ bi) {
    int b = blockIdx.x >> 5;
    int g = blockIdx.x & 31;
    const float* xp = x + ((size_t)b * CH + g * CPG) * HW;
    __nv_bfloat16* op = g_hnb + ((size_t)b * CH + g * CPG) * HW;
    int t = threadIdx.x;
    const int TOT = CPG * HW;

    float s = 0.f, s2 = 0.f;
    for (int i = t * 4; i < TOT; i += 1024) {
        float4 v = *(const float4*)&xp[i];
        s  += v.x + v.y + v.z + v.w;
        s2 += v.x * v.x + v.y * v.y + v.z * v.z + v.w * v.w;
    }
    __shared__ float rs[256], rs2[256];
    rs[t] = s; rs2[t] = s2;
    __syncthreads();
    for (int o = 128; o > 0; o >>= 1) {
        if (t < o) { rs[t] += rs[t + o]; rs2[t] += rs2[t + o]; }
        __syncthreads();
    }
    float mean = rs[0] * (1.0f / TOT);
    float var  = rs2[0] * (1.0f / TOT) - mean * mean;
    float inv  = rsqrtf(var + 1e-6f);

    for (int i = t * 4; i < TOT; i += 1024) {
        int c = g * CPG + (i >> 12);
        float a  = sc[c] * inv;
        float bb = bi[c] - mean * a;
        float4 v = *(const float4*)&xp[i];
        __nv_bfloat162 p0 = __float22bfloat162_rn(make_float2(v.x * a + bb, v.y * a + bb));
        __nv_bfloat162 p1 = __float22bfloat162_rn(make_float2(v.z * a + bb, v.w * a + bb));
        uint2 pk = {*(uint32_t*)&p0, *(uint32_t*)&p1};
        *(uint2*)&op[i] = pk;
    }
}

// ============== Row softmax over m: reads fp32 S, writes bf16 P =============
__global__ void __launch_bounds__(256) softmax_kernel() {
    size_t row = blockIdx.x;                 // b*4096 + n
    const float* p = g_s + row * (size_t)HW;
    __nv_bfloat16* q = g_p + row * (size_t)HW;
    int t = threadIdx.x;

    float4 v[4];
    float mx = -1e30f;
#pragma unroll
    for (int i = 0; i < 4; i++) {
        v[i] = *(const float4*)&p[t * 4 + i * 1024];
        mx = fmaxf(mx, fmaxf(fmaxf(v[i].x, v[i].y), fmaxf(v[i].z, v[i].w)));
    }
    __shared__ float red[256];
    red[t] = mx; __syncthreads();
    for (int o = 128; o > 0; o >>= 1) {
        if (t < o) red[t] = fmaxf(red[t], red[t + o]);
        __syncthreads();
    }
    mx = red[0];
    __syncthreads();

    float sum = 0.f;
#pragma unroll
    for (int i = 0; i < 4; i++) {
        v[i].x = __expf(v[i].x - mx); v[i].y = __expf(v[i].y - mx);
        v[i].z = __expf(v[i].z - mx); v[i].w = __expf(v[i].w - mx);
        sum += v[i].x + v[i].y + v[i].z + v[i].w;
    }
    red[t] = sum; __syncthreads();
    for (int o = 128; o > 0; o >>= 1) {
        if (t < o) red[t] += red[t + o];
        __syncthreads();
    }
    float inv = 1.0f / red[0];
#pragma unroll
    for (int i = 0; i < 4; i++) {
        __nv_bfloat162 o0 = __float22bfloat162_rn(make_float2(v[i].x * inv, v[i].y * inv));
        __nv_bfloat162 o1 = __float22bfloat162_rn(make_float2(v[i].z * inv, v[i].w * inv));
        uint2 pk = {*(uint32_t*)&o0, *(uint32_t*)&o1};
        *(uint2*)&q[t * 4 + i * 1024] = pk;
    }
}

// ============================== launch ======================================
extern "C" void kernel_launch(void* const* d_in, const int* in_sizes, int n_in,
                              void* d_out, int out_size) {
    const float* x    = (const float*)d_in[0];
    const float* gns  = (const float*)d_in[1];
    const float* gnb  = (const float*)d_in[2];
    const float* wq   = (const float*)d_in[3];
    const float* bq   = (const float*)d_in[4];
    const float* wk   = (const float*)d_in[5];
    const float* bk   = (const float*)d_in[6];
    const float* wv   = (const float*)d_in[7];
    const float* bv   = (const float*)d_in[8];
    const float* wp   = (const float*)d_in[9];
    const float* bp   = (const float*)d_in[10];
    float* out = (float*)d_out;

    gn_kernel<<<BSZ * 32, 256>>>(x, gns, gnb);
    wconv_kernel<<<64, 256>>>(wq, wk, wv, wp);
    // QKV: q/k/v[c][n] = W hn + b
    gemm_bf16<0><<<dim3(HW / 128, 6, BSZ), 256>>>(bq, bk, bv, nullptr, nullptr);
    // scores: S[n][m] = q . k / 16
    gemm_bf16<1><<<dim3(HW / 128, HW / 128, BSZ), 256>>>(nullptr, nullptr, nullptr, nullptr, nullptr);
    softmax_kernel<<<BSZ * HW, 256>>>();
    // PV: ao[c][n] = v P^T
    gemm_bf16<2><<<dim3(HW / 128, CH / 128, BSZ), 256>>>(nullptr, nullptr, nullptr, nullptr, nullptr);
    // proj + residual
    gemm_bf16<3><<<dim3(HW / 128, CH / 128, BSZ), 256>>>(bp, nullptr, nullptr, x, out);
}

// round 6
// speedup vs baseline: 5.4417x; 1.0880x over previous
#include <cuda_runtime.h>
#include <cuda_bf16.h>
#include <cuda_fp16.h>
#include <math.h>
#include <stdint.h>

// Shapes (fixed by the problem)
#define BSZ 8
#define CH  256
#define HW  4096            // 64*64 tokens
#define CPG 8               // channels per group

// ---------------- scratch (static device globals; no runtime alloc) --------
__device__ __nv_bfloat16 g_hnb[(size_t)BSZ * CH * HW];          // groupnormed x, [b][c][n]
__device__ __nv_bfloat16 g_q2[(size_t)BSZ * CH * HW];           // q [b][c][n]
__device__ __nv_bfloat16 g_k2[(size_t)BSZ * CH * HW];           // k [b][c][n]
__device__ __nv_bfloat16 g_v2[(size_t)BSZ * CH * HW];           // v [b][c][n]
__device__ __nv_bfloat16 g_aob[(size_t)BSZ * CH * HW];          // attn out [b][c][n]
__device__ __half        g_s [(size_t)BSZ * HW * HW];           // scores fp16 256MB
__device__ __nv_bfloat16 g_p [(size_t)BSZ * HW * HW];           // probs bf16 256MB
__device__ __nv_bfloat16 g_wb[3 * CH * CH];                     // wq,wk,wv bf16
__device__ __nv_bfloat16 g_wpb[CH * CH];                        // wproj bf16

// ====================== PTX helpers (sm_80+ features only) ==================
__device__ __forceinline__ uint32_t smem_u32(const void* p) {
    uint32_t a;
    asm("{ .reg .u64 t; cvta.to.shared.u64 t, %1; cvt.u32.u64 %0, t; }" : "=r"(a) : "l"(p));
    return a;
}
__device__ __forceinline__ void ldsm_x4(uint32_t* r, uint32_t addr) {
    asm volatile("ldmatrix.sync.aligned.m8n8.x4.shared.b16 {%0,%1,%2,%3}, [%4];"
        : "=r"(r[0]), "=r"(r[1]), "=r"(r[2]), "=r"(r[3]) : "r"(addr));
}
__device__ __forceinline__ void ldsm_x4_t(uint32_t* r, uint32_t addr) {
    asm volatile("ldmatrix.sync.aligned.m8n8.x4.trans.shared.b16 {%0,%1,%2,%3}, [%4];"
        : "=r"(r[0]), "=r"(r[1]), "=r"(r[2]), "=r"(r[3]) : "r"(addr));
}
__device__ __forceinline__ void mma_bf16(float* d, const uint32_t* a, const uint32_t* b) {
    asm volatile("mma.sync.aligned.m16n8k16.row.col.f32.bf16.bf16.f32 "
        "{%0,%1,%2,%3}, {%4,%5,%6,%7}, {%8,%9}, {%0,%1,%2,%3};"
        : "+f"(d[0]), "+f"(d[1]), "+f"(d[2]), "+f"(d[3])
        : "r"(a[0]), "r"(a[1]), "r"(a[2]), "r"(a[3]), "r"(b[0]), "r"(b[1]));
}
#define CP_ASYNC16(s, g) asm volatile("cp.async.cg.shared.global [%0], [%1], 16;" :: "r"(s), "l"(g))
#define CP_COMMIT()      asm volatile("cp.async.commit_group;" ::: "memory")
#define CP_WAIT1()       asm volatile("cp.async.wait_group 1;" ::: "memory")
#define CP_WAIT0()       asm volatile("cp.async.wait_group 0;" ::: "memory")

// Tile geometry, K-chunk = 64.
// Normal (K-major [m][k]):  128 rows x 64 bf16 (128B), padded stride 144B.
// Trans  ([k][m]):          64 k-rows x 128 bf16 (256B), padded stride 272B.
static constexpr int ROW_N  = 144;
static constexpr int ROW_T  = 272;
static constexpr int TILE_N = 128 * ROW_N;   // 18432
static constexpr int TILE_T = 64 * ROW_T;    // 17408
static constexpr int KCH    = 64;

template <bool TR>
__device__ __forceinline__ void fill_tile(const __nv_bfloat16* __restrict__ g,
                                          size_t stride, uint32_t sbase, int t) {
#pragma unroll
    for (int it = 0; it < 4; it++) {
        int chunk = t + it * 256;           // 1024 chunks of 16B
        if (TR) {
            int row = chunk >> 4, c16 = chunk & 15;
            CP_ASYNC16(sbase + row * ROW_T + c16 * 16,
                       g + (size_t)row * stride + c16 * 8);
        } else {
            int row = chunk >> 3, c16 = chunk & 7;
            CP_ASYNC16(sbase + row * ROW_N + c16 * 16,
                       g + (size_t)row * stride + c16 * 8);
        }
    }
}

// ===================== Unified HMMA GEMM ====================================
// D[128][128] tile = A x B^T over K; CTA tile 128x128, warps 2(m) x 4(n).
// MODE 0: QKV   q/k/v[c][n] = W[o][c] * hn[c][n] + bias      (A normal, B trans)
// MODE 1: scores S[n][m] = (1/16) q[c][n]^T k[c][m] -> fp16  (A trans,  B trans)
// MODE 2: PV    ao[c][n] = v[c][m] * P[n][m]                 (A normal, B normal)
// MODE 3: proj  out = x + Wp[o][c] * ao[c][n] + bias         (A normal, B trans)
template <int MODE>
__global__ void __launch_bounds__(256) gemm_bf16(const float* __restrict__ bias0,
                                                 const float* __restrict__ bias1,
                                                 const float* __restrict__ bias2,
                                                 const float* __restrict__ xres,
                                                 float* __restrict__ outp) {
    constexpr bool AT = (MODE == 1);
    constexpr bool BT = (MODE != 2);
    constexpr int  K  = (MODE == 2) ? HW : CH;
    constexpr int  NC = K / KCH;
    constexpr int  ATILE = AT ? TILE_T : TILE_N;
    constexpr int  BTILE = BT ? TILE_T : TILE_N;
    constexpr int  STAGE = ATILE + BTILE;

    int z = blockIdx.z;
    int which = 0, m0, n0;
    if (MODE == 0)      { which = blockIdx.y >> 1; m0 = (blockIdx.y & 1) * 128; n0 = blockIdx.x * 128; }
    else if (MODE == 2) { m0 = blockIdx.x * 128; n0 = blockIdx.y * 128; }   // x = c-tile (L2 pairing)
    else                { m0 = blockIdx.y * 128; n0 = blockIdx.x * 128; }

    const __nv_bfloat16 *A, *B;
    size_t astride, bstride;
    if (MODE == 0) {
        A = g_wb + (size_t)which * CH * CH + (size_t)m0 * CH;  astride = CH;
        B = g_hnb + (size_t)z * CH * HW + n0;                  bstride = HW;
    } else if (MODE == 1) {
        A = g_q2 + (size_t)z * CH * HW + m0;                   astride = HW;
        B = g_k2 + (size_t)z * CH * HW + n0;                   bstride = HW;
    } else if (MODE == 2) {
        A = g_v2 + (size_t)z * CH * HW + (size_t)m0 * HW;      astride = HW;
        B = g_p  + (size_t)z * HW * HW + (size_t)n0 * HW;      bstride = HW;
    } else {
        A = g_wpb + (size_t)m0 * CH;                           astride = CH;
        B = g_aob + (size_t)z * CH * HW + n0;                  bstride = HW;
    }
    auto a_off = [&](int c) -> size_t { return AT ? (size_t)c * KCH * astride : (size_t)c * KCH; };
    auto b_off = [&](int c) -> size_t { return BT ? (size_t)c * KCH * bstride : (size_t)c * KCH; };

    extern __shared__ __align__(16) char smem[];
    uint32_t sb = smem_u32(smem);
    int t = threadIdx.x, wid = t >> 5, lane = t & 31;
    int wm = wid >> 2, wn = wid & 3;

    float acc[4][4][4];
#pragma unroll
    for (int i = 0; i < 4; i++)
#pragma unroll
        for (int j = 0; j < 4; j++)
#pragma unroll
            for (int r = 0; r < 4; r++) acc[i][j][r] = 0.f;

    // prologue: fill stages 0 and 1
    fill_tile<AT>(A, astride, sb, t);
    fill_tile<BT>(B, bstride, sb + ATILE, t);
    CP_COMMIT();
    if (NC > 1) {
        fill_tile<AT>(A + a_off(1), astride, sb + STAGE, t);
        fill_tile<BT>(B + b_off(1), bstride, sb + STAGE + ATILE, t);
        CP_COMMIT();
    }

#pragma unroll 1
    for (int c = 0; c < NC; c++) {
        if (c + 1 < NC) { CP_WAIT1(); } else { CP_WAIT0(); }
        __syncthreads();   // stage c visible; all warps done reading stage c-1 (buffer (c+2)%3)
        if (c + 2 < NC) {
            uint32_t nb = sb + ((c + 2) % 3) * STAGE;
            fill_tile<AT>(A + a_off(c + 2), astride, nb, t);
            fill_tile<BT>(B + b_off(c + 2), bstride, nb + ATILE, t);
            CP_COMMIT();
        }
        uint32_t ab = sb + (c % 3) * STAGE;
        uint32_t bb = ab + ATILE;
#pragma unroll
        for (int ks = 0; ks < KCH / 16; ks++) {
            uint32_t a_frag[4][4];
            uint32_t b_frag[4][2];
#pragma unroll
            for (int mt = 0; mt < 4; mt++) {
                if (AT) {
                    int krow = (lane & 7) + ((lane >> 4) << 3) + ks * 16;
                    int mcol = wm * 64 + mt * 16 + ((lane >> 3) & 1) * 8;
                    ldsm_x4_t(a_frag[mt], ab + krow * ROW_T + mcol * 2);
                } else {
                    int row = wm * 64 + mt * 16 + (lane & 15);
                    ldsm_x4(a_frag[mt], ab + row * ROW_N + (ks * 16 + (lane >> 4) * 8) * 2);
                }
            }
#pragma unroll
            for (int p = 0; p < 2; p++) {
                uint32_t q[4];
                if (BT) {
                    int krow = (lane & 7) + ((lane >> 4) << 3) + ks * 16;
                    int ncol = wn * 32 + p * 16 + ((lane >> 3) & 1) * 8;
                    ldsm_x4_t(q, bb + krow * ROW_T + ncol * 2);
                } else {
                    int row = wn * 32 + p * 16 + (lane & 15);
                    ldsm_x4(q, bb + row * ROW_N + (ks * 16 + (lane >> 4) * 8) * 2);
                }
                b_frag[2 * p][0]     = q[0]; b_frag[2 * p][1]     = q[2];
                b_frag[2 * p + 1][0] = q[1]; b_frag[2 * p + 1][1] = q[3];
            }
#pragma unroll
            for (int mt = 0; mt < 4; mt++)
#pragma unroll
                for (int nt = 0; nt < 4; nt++)
                    mma_bf16(acc[mt][nt], a_frag[mt], b_frag[nt]);
        }
    }

    // epilogue: d0 (r,c) d1 (r,c+1) d2 (r+8,c) d3 (r+8,c+1)
    int r0 = m0 + wm * 64 + (lane >> 2);
    int c0 = n0 + wn * 32 + (lane & 3) * 2;

    if (MODE == 1) {
        __half* D = g_s + (size_t)z * HW * HW;
#pragma unroll
        for (int mt = 0; mt < 4; mt++)
#pragma unroll
            for (int nt = 0; nt < 4; nt++) {
                size_t base = (size_t)(r0 + mt * 16) * HW + c0 + nt * 8;
                *(__half2*)&D[base] =
                    __floats2half2_rn(acc[mt][nt][0] * 0.0625f, acc[mt][nt][1] * 0.0625f);
                *(__half2*)&D[base + 8 * HW] =
                    __floats2half2_rn(acc[mt][nt][2] * 0.0625f, acc[mt][nt][3] * 0.0625f);
            }
    } else if (MODE == 0 || MODE == 2) {
        __nv_bfloat16* D;
        const float* bias = nullptr;
        if (MODE == 0) {
            D = ((which == 0) ? g_q2 : (which == 1) ? g_k2 : g_v2) + (size_t)z * CH * HW;
            bias = (which == 0) ? bias0 : (which == 1) ? bias1 : bias2;
        } else {
            D = g_aob + (size_t)z * CH * HW;
        }
#pragma unroll
        for (int mt = 0; mt < 4; mt++) {
            int r = r0 + mt * 16;
            float b1 = (MODE == 0) ? bias[r] : 0.f;
            float b2 = (MODE == 0) ? bias[r + 8] : 0.f;
#pragma unroll
            for (int nt = 0; nt < 4; nt++) {
                size_t base = (size_t)r * HW + c0 + nt * 8;
                __nv_bfloat162 o0 = __float22bfloat162_rn(
                    make_float2(acc[mt][nt][0] + b1, acc[mt][nt][1] + b1));
                __nv_bfloat162 o1 = __float22bfloat162_rn(
                    make_float2(acc[mt][nt][2] + b2, acc[mt][nt][3] + b2));
                *(__nv_bfloat162*)&D[base]          = o0;
                *(__nv_bfloat162*)&D[base + 8 * HW] = o1;
            }
        }
    } else {  // MODE 3: proj + bias + residual, fp32 out
#pragma unroll
        for (int mt = 0; mt < 4; mt++) {
            int r = r0 + mt * 16;
            float b1 = bias0[r], b2 = bias0[r + 8];
#pragma unroll
            for (int nt = 0; nt < 4; nt++) {
                size_t idx = ((size_t)z * CH + r) * HW + c0 + nt * 8;
                float2 x0 = *(const float2*)&xres[idx];
                float2 x1 = *(const float2*)&xres[idx + 8 * HW];
                float2 v0 = {acc[mt][nt][0] + b1 + x0.x, acc[mt][nt][1] + b1 + x0.y};
                float2 v1 = {acc[mt][nt][2] + b2 + x1.x, acc[mt][nt][3] + b2 + x1.y};
                *(float2*)&outp[idx]          = v0;
                *(float2*)&outp[idx + 8 * HW] = v1;
            }
        }
    }
}

// ================= weights fp32 -> bf16 (tiny, once per call) ===============
__global__ void __launch_bounds__(256) wconv_kernel(const float* __restrict__ wq,
                                                    const float* __restrict__ wk,
                                                    const float* __restrict__ wv,
                                                    const float* __restrict__ wp) {
    int i = blockIdx.x * 256 + threadIdx.x;      // 16384 float4s per matrix
    const float* srcs[4] = {wq, wk, wv, wp};
    __nv_bfloat16* dsts[4] = {g_wb, g_wb + CH * CH, g_wb + 2 * CH * CH, g_wpb};
#pragma unroll
    for (int m = 0; m < 4; m++) {
        float4 a = ((const float4*)srcs[m])[i];
        __nv_bfloat162 p0 = __float22bfloat162_rn(make_float2(a.x, a.y));
        __nv_bfloat162 p1 = __float22bfloat162_rn(make_float2(a.z, a.w));
        uint2 pk = {*(uint32_t*)&p0, *(uint32_t*)&p1};
        *(uint2*)&dsts[m][i * 4] = pk;
    }
}

// ============================ GroupNorm -> bf16 =============================
__global__ void __launch_bounds__(256) gn_kernel(const float* __restrict__ x,
                                                 const float* __restrict__ sc,
                                                 const float* __restrict__ bi) {
    int b = blockIdx.x >> 5;
    int g = blockIdx.x & 31;
    const float* xp = x + ((size_t)b * CH + g * CPG) * HW;
    __nv_bfloat16* op = g_hnb + ((size_t)b * CH + g * CPG) * HW;
    int t = threadIdx.x;
    const int TOT = CPG * HW;

    float s = 0.f, s2 = 0.f;
    for (int i = t * 4; i < TOT; i += 1024) {
        float4 v = *(const float4*)&xp[i];
        s  += v.x + v.y + v.z + v.w;
        s2 += v.x * v.x + v.y * v.y + v.z * v.z + v.w * v.w;
    }
    __shared__ float rs[256], rs2[256];
    rs[t] = s; rs2[t] = s2;
    __syncthreads();
    for (int o = 128; o > 0; o >>= 1) {
        if (t < o) { rs[t] += rs[t + o]; rs2[t] += rs2[t + o]; }
        __syncthreads();
    }
    float mean = rs[0] * (1.0f / TOT);
    float var  = rs2[0] * (1.0f / TOT) - mean * mean;
    float inv  = rsqrtf(var + 1e-6f);

    for (int i = t * 4; i < TOT; i += 1024) {
        int c = g * CPG + (i >> 12);
        float a  = sc[c] * inv;
        float bb = bi[c] - mean * a;
        float4 v = *(const float4*)&xp[i];
        __nv_bfloat162 p0 = __float22bfloat162_rn(make_float2(v.x * a + bb, v.y * a + bb));
        __nv_bfloat162 p1 = __float22bfloat162_rn(make_float2(v.z * a + bb, v.w * a + bb));
        uint2 pk = {*(uint32_t*)&p0, *(uint32_t*)&p1};
        *(uint2*)&op[i] = pk;
    }
}

// ============== Row softmax over m: reads fp16 S, writes bf16 P =============
__global__ void __launch_bounds__(256) softmax_kernel() {
    size_t row = blockIdx.x;                 // b*4096 + n
    const __half* p = g_s + row * (size_t)HW;
    __nv_bfloat16* q = g_p + row * (size_t)HW;
    int t = threadIdx.x;

    uint4 raw[2];
    float v[16];
    float mx = -1e30f;
#pragma unroll
    for (int j = 0; j < 2; j++) {
        raw[j] = *(const uint4*)&p[t * 8 + j * 2048];
        const uint32_t* w = (const uint32_t*)&raw[j];
#pragma unroll
        for (int h = 0; h < 4; h++) {
            float2 f = __half22float2(*(const __half2*)&w[h]);
            v[j * 8 + h * 2]     = f.x;
            v[j * 8 + h * 2 + 1] = f.y;
            mx = fmaxf(mx, fmaxf(f.x, f.y));
        }
    }
    __shared__ float red[256];
    red[t] = mx; __syncthreads();
    for (int o = 128; o > 0; o >>= 1) {
        if (t < o) red[t] = fmaxf(red[t], red[t + o]);
        __syncthreads();
    }
    mx = red[0];
    __syncthreads();

    float sum = 0.f;
#pragma unroll
    for (int i = 0; i < 16; i++) { v[i] = __expf(v[i] - mx); sum += v[i]; }
    red[t] = sum; __syncthreads();
    for (int o = 128; o > 0; o >>= 1) {
        if (t < o) red[t] += red[t + o];
        __syncthreads();
    }
    float inv = 1.0f / red[0];
#pragma unroll
    for (int j = 0; j < 2; j++) {
        uint32_t w[4];
#pragma unroll
        for (int h = 0; h < 4; h++) {
            __nv_bfloat162 o2 = __float22bfloat162_rn(
                make_float2(v[j * 8 + h * 2] * inv, v[j * 8 + h * 2 + 1] * inv));
            w[h] = *(uint32_t*)&o2;
        }
        *(uint4*)&q[t * 8 + j * 2048] = *(uint4*)w;
    }
}

// ============================== launch ======================================
extern "C" void kernel_launch(void* const* d_in, const int* in_sizes, int n_in,
                              void* d_out, int out_size) {
    const float* x    = (const float*)d_in[0];
    const float* gns  = (const float*)d_in[1];
    const float* gnb  = (const float*)d_in[2];
    const float* wq   = (const float*)d_in[3];
    const float* bq   = (const float*)d_in[4];
    const float* wk   = (const float*)d_in[5];
    const float* bk   = (const float*)d_in[6];
    const float* wv   = (const float*)d_in[7];
    const float* bv   = (const float*)d_in[8];
    const float* wp   = (const float*)d_in[9];
    const float* bp   = (const float*)d_in[10];
    float* out = (float*)d_out;

    constexpr int SM_QKV    = 3 * (TILE_N + TILE_T);  // 107520
    constexpr int SM_SCORES = 3 * (2 * TILE_T);       // 104448
    constexpr int SM_PV     = 3 * (2 * TILE_N);       // 110592

    cudaFuncSetAttribute(gemm_bf16<0>, cudaFuncAttributeMaxDynamicSharedMemorySize, SM_QKV);
    cudaFuncSetAttribute(gemm_bf16<1>, cudaFuncAttributeMaxDynamicSharedMemorySize, SM_SCORES);
    cudaFuncSetAttribute(gemm_bf16<2>, cudaFuncAttributeMaxDynamicSharedMemorySize, SM_PV);
    cudaFuncSetAttribute(gemm_bf16<3>, cudaFuncAttributeMaxDynamicSharedMemorySize, SM_QKV);

    gn_kernel<<<BSZ * 32, 256>>>(x, gns, gnb);
    wconv_kernel<<<64, 256>>>(wq, wk, wv, wp);
    // QKV: q/k/v[c][n] = W hn + b
    gemm_bf16<0><<<dim3(HW / 128, 6, BSZ), 256, SM_QKV>>>(bq, bk, bv, nullptr, nullptr);
    // scores: S[n][m] = q . k / 16  -> fp16
    gemm_bf16<1><<<dim3(HW / 128, HW / 128, BSZ), 256, SM_SCORES>>>(nullptr, nullptr, nullptr, nullptr, nullptr);
    softmax_kernel<<<BSZ * HW, 256>>>();
    // PV: ao[c][n] = v P^T   (x = c-tile so the 2 c-tiles of an n-tile share P in L2)
    gemm_bf16<2><<<dim3(CH / 128, HW / 128, BSZ), 256, SM_PV>>>(nullptr, nullptr, nullptr, nullptr, nullptr);
    // proj + residual
    gemm_bf16<3><<<dim3(HW / 128, CH / 128, BSZ), 256, SM_QKV>>>(bp, nullptr, nullptr, x, out);
}

// round 7
// speedup vs baseline: 6.1363x; 1.1276x over previous
#include <cuda_runtime.h>
#include <cuda_bf16.h>
#include <cuda_fp16.h>
#include <math.h>
#include <stdint.h>

// Shapes (fixed by the problem)
#define BSZ 8
#define CH  256
#define HW  4096            // 64*64 tokens
#define CPG 8               // channels per group

// ---------------- scratch (static device globals; no runtime alloc) --------
__device__ __nv_bfloat16 g_hnb[(size_t)BSZ * CH * HW];          // groupnormed x, [b][c][n]
__device__ __half        g_q2[(size_t)BSZ * CH * HW];           // q [b][c][n] fp16
__device__ __half        g_k2[(size_t)BSZ * CH * HW];           // k [b][c][n] fp16
__device__ __half        g_v2[(size_t)BSZ * CH * HW];           // v [b][c][n] fp16
__device__ __nv_bfloat16 g_aob[(size_t)BSZ * CH * HW];          // attn out [b][c][n] bf16
__device__ __half        g_s [(size_t)BSZ * HW * HW];           // scores fp16 256MB
__device__ __half        g_p [(size_t)BSZ * HW * HW];           // probs fp16 256MB
__device__ __nv_bfloat16 g_wb[3 * CH * CH];                     // wq,wk,wv bf16
__device__ __nv_bfloat16 g_wpb[CH * CH];                        // wproj bf16

// ====================== PTX helpers (sm_80+ features only) ==================
__device__ __forceinline__ uint32_t smem_u32(const void* p) {
    uint32_t a;
    asm("{ .reg .u64 t; cvta.to.shared.u64 t, %1; cvt.u32.u64 %0, t; }" : "=r"(a) : "l"(p));
    return a;
}
__device__ __forceinline__ void ldsm_x4(uint32_t* r, uint32_t addr) {
    asm volatile("ldmatrix.sync.aligned.m8n8.x4.shared.b16 {%0,%1,%2,%3}, [%4];"
        : "=r"(r[0]), "=r"(r[1]), "=r"(r[2]), "=r"(r[3]) : "r"(addr));
}
__device__ __forceinline__ void ldsm_x4_t(uint32_t* r, uint32_t addr) {
    asm volatile("ldmatrix.sync.aligned.m8n8.x4.trans.shared.b16 {%0,%1,%2,%3}, [%4];"
        : "=r"(r[0]), "=r"(r[1]), "=r"(r[2]), "=r"(r[3]) : "r"(addr));
}
__device__ __forceinline__ void mma_bf16(float* d, const uint32_t* a, const uint32_t* b) {
    asm volatile("mma.sync.aligned.m16n8k16.row.col.f32.bf16.bf16.f32 "
        "{%0,%1,%2,%3}, {%4,%5,%6,%7}, {%8,%9}, {%0,%1,%2,%3};"
        : "+f"(d[0]), "+f"(d[1]), "+f"(d[2]), "+f"(d[3])
        : "r"(a[0]), "r"(a[1]), "r"(a[2]), "r"(a[3]), "r"(b[0]), "r"(b[1]));
}
__device__ __forceinline__ void mma_f16(uint32_t* c, const uint32_t* a, const uint32_t* b) {
    asm volatile("mma.sync.aligned.m16n8k16.row.col.f16.f16.f16.f16 "
        "{%0,%1}, {%2,%3,%4,%5}, {%6,%7}, {%0,%1};"
        : "+r"(c[0]), "+r"(c[1])
        : "r"(a[0]), "r"(a[1]), "r"(a[2]), "r"(a[3]), "r"(b[0]), "r"(b[1]));
}
#define CP_ASYNC16(s, g) asm volatile("cp.async.cg.shared.global [%0], [%1], 16;" :: "r"(s), "l"(g))
#define CP_COMMIT()      asm volatile("cp.async.commit_group;" ::: "memory")
#define CP_WAIT1()       asm volatile("cp.async.wait_group 1;" ::: "memory")
#define CP_WAIT0()       asm volatile("cp.async.wait_group 0;" ::: "memory")

// Tile geometry, K-chunk = 64 (16-bit elements, 2B each).
// Normal (K-major [m][k]):  128 rows x 64 el (128B), padded stride 144B.
// Trans  ([k][m]):          64 k-rows x 128 el (256B), padded stride 272B.
static constexpr int ROW_N  = 144;
static constexpr int ROW_T  = 272;
static constexpr int TILE_N = 128 * ROW_N;   // 18432
static constexpr int TILE_T = 64 * ROW_T;    // 17408
static constexpr int KCH    = 64;

template <bool TR, typename T>
__device__ __forceinline__ void fill_tile(const T* __restrict__ g,
                                          size_t stride, uint32_t sbase, int t) {
#pragma unroll
    for (int it = 0; it < 4; it++) {
        int chunk = t + it * 256;           // 1024 chunks of 16B
        if (TR) {
            int row = chunk >> 4, c16 = chunk & 15;
            CP_ASYNC16(sbase + row * ROW_T + c16 * 16,
                       g + (size_t)row * stride + c16 * 8);
        } else {
            int row = chunk >> 3, c16 = chunk & 7;
            CP_ASYNC16(sbase + row * ROW_N + c16 * 16,
                       g + (size_t)row * stride + c16 * 8);
        }
    }
}

// ============= f16-accumulate HMMA GEMM (scores & PV) =======================
// D[128][128] tile = A x B^T over K; warps 2(m) x 4(n), 2-stage cp.async.
// MODE 1: scores S[n][m] = (1/16) q[c][n]^T k[c][m] -> fp16   (both trans)
// MODE 2: PV    ao[c][n] = v[c][m] * P[n][m] -> bf16          (both normal)
template <int MODE>
__global__ void __launch_bounds__(256, 3) gemm_f16() {
    constexpr bool TRANS = (MODE == 1);
    constexpr int  K     = (MODE == 2) ? HW : CH;
    constexpr int  NC    = K / KCH;
    constexpr int  TILE  = TRANS ? TILE_T : TILE_N;
    constexpr int  ROW   = TRANS ? ROW_T : ROW_N;
    constexpr int  STAGE = 2 * TILE;

    int z = blockIdx.z;
    int m0, n0;
    if (MODE == 2) { m0 = blockIdx.x * 128; n0 = blockIdx.y * 128; }  // c-tile fastest: L2 pairing on P
    else           { m0 = blockIdx.y * 128; n0 = blockIdx.x * 128; }

    const __half *A, *B;
    if (MODE == 1) {
        A = g_q2 + (size_t)z * CH * HW + m0;               // [c][n], trans
        B = g_k2 + (size_t)z * CH * HW + n0;
    } else {
        A = g_v2 + (size_t)z * CH * HW + (size_t)m0 * HW;  // [c][m], normal
        B = g_p  + (size_t)z * HW * HW + (size_t)n0 * HW;  // [n][m], normal
    }
    const size_t stride = HW;
    auto adv = [&](int c) -> size_t { return TRANS ? (size_t)c * KCH * stride : (size_t)c * KCH; };

    extern __shared__ __align__(16) char smem[];
    uint32_t sb = smem_u32(smem);
    int t = threadIdx.x, wid = t >> 5, lane = t & 31;
    int wm = wid >> 2, wn = wid & 3;

    uint32_t acc[4][4][2];
#pragma unroll
    for (int i = 0; i < 4; i++)
#pragma unroll
        for (int j = 0; j < 4; j++) { acc[i][j][0] = 0u; acc[i][j][1] = 0u; }

    fill_tile<TRANS>(A, stride, sb, t);
    fill_tile<TRANS>(B, stride, sb + TILE, t);
    CP_COMMIT();

#pragma unroll 1
    for (int c = 0; c < NC; c++) {
        int buf = c & 1;
        if (c + 1 < NC) {
            uint32_t nb = sb + ((c + 1) & 1) * STAGE;
            fill_tile<TRANS>(A + adv(c + 1), stride, nb, t);
            fill_tile<TRANS>(B + adv(c + 1), stride, nb + TILE, t);
            CP_COMMIT();
            CP_WAIT1();
        } else {
            CP_WAIT0();
        }
        __syncthreads();

        uint32_t ab = sb + buf * STAGE;
        uint32_t bb = ab + TILE;
#pragma unroll
        for (int ks = 0; ks < KCH / 16; ks++) {
            uint32_t a_frag[4][4];
            uint32_t b_frag[4][2];
#pragma unroll
            for (int mt = 0; mt < 4; mt++) {
                if (TRANS) {
                    int krow = (lane & 7) + ((lane >> 4) << 3) + ks * 16;
                    int mcol = wm * 64 + mt * 16 + ((lane >> 3) & 1) * 8;
                    ldsm_x4_t(a_frag[mt], ab + krow * ROW + mcol * 2);
                } else {
                    int row = wm * 64 + mt * 16 + (lane & 15);
                    ldsm_x4(a_frag[mt], ab + row * ROW + (ks * 16 + (lane >> 4) * 8) * 2);
                }
            }
#pragma unroll
            for (int p = 0; p < 2; p++) {
                uint32_t q[4];
                if (TRANS) {
                    int krow = (lane & 7) + ((lane >> 4) << 3) + ks * 16;
                    int ncol = wn * 32 + p * 16 + ((lane >> 3) & 1) * 8;
                    ldsm_x4_t(q, bb + krow * ROW + ncol * 2);
                } else {
                    int row = wn * 32 + p * 16 + (lane & 15);
                    ldsm_x4(q, bb + row * ROW + (ks * 16 + (lane >> 4) * 8) * 2);
                }
                b_frag[2 * p][0]     = q[0]; b_frag[2 * p][1]     = q[2];
                b_frag[2 * p + 1][0] = q[1]; b_frag[2 * p + 1][1] = q[3];
            }
#pragma unroll
            for (int mt = 0; mt < 4; mt++)
#pragma unroll
                for (int nt = 0; nt < 4; nt++)
                    mma_f16(acc[mt][nt], a_frag[mt], b_frag[nt]);
        }
        __syncthreads();
    }

    // epilogue: c0 = (r, col..col+1), c1 = (r+8, col..col+1)
    int r0 = m0 + wm * 64 + (lane >> 2);
    int c0 = n0 + wn * 32 + (lane & 3) * 2;

    if (MODE == 1) {
        __half* D = g_s + (size_t)z * HW * HW;
        const __half2 sc = __half2half2(__float2half(0.0625f));
#pragma unroll
        for (int mt = 0; mt < 4; mt++)
#pragma unroll
            for (int nt = 0; nt < 4; nt++) {
                size_t base = (size_t)(r0 + mt * 16) * HW + c0 + nt * 8;
                __half2 h0 = *(__half2*)&acc[mt][nt][0];
                __half2 h1 = *(__half2*)&acc[mt][nt][1];
                *(__half2*)&D[base]          = __hmul2(h0, sc);
                *(__half2*)&D[base + 8 * HW] = __hmul2(h1, sc);
            }
    } else {
        __nv_bfloat16* D = g_aob + (size_t)z * CH * HW;
#pragma unroll
        for (int mt = 0; mt < 4; mt++)
#pragma unroll
            for (int nt = 0; nt < 4; nt++) {
                size_t base = (size_t)(r0 + mt * 16) * HW + c0 + nt * 8;
                float2 f0 = __half22float2(*(__half2*)&acc[mt][nt][0]);
                float2 f1 = __half22float2(*(__half2*)&acc[mt][nt][1]);
                *(__nv_bfloat162*)&D[base]          = __float22bfloat162_rn(f0);
                *(__nv_bfloat162*)&D[base + 8 * HW] = __float22bfloat162_rn(f1);
            }
    }
}

// ============= bf16 / f32-acc HMMA GEMM (QKV & proj), K=256 =================
// MODE 0: QKV   q/k/v[c][n] = W[o][c] * hn[c][n] + bias -> fp16  (A normal, B trans)
// MODE 3: proj  out = x + Wp[o][c] * ao[c][n] + bias -> fp32     (A normal, B trans)
template <int MODE>
__global__ void __launch_bounds__(256) gemm_bf16(const float* __restrict__ bias0,
                                                 const float* __restrict__ bias1,
                                                 const float* __restrict__ bias2,
                                                 const float* __restrict__ xres,
                                                 float* __restrict__ outp) {
    constexpr int NC = CH / KCH;
    constexpr int STAGE = TILE_N + TILE_T;

    int n0 = blockIdx.x * 128, z = blockIdx.z;
    int which = 0, m0;
    if (MODE == 0) { which = blockIdx.y >> 1; m0 = (blockIdx.y & 1) * 128; }
    else           { m0 = blockIdx.y * 128; }

    const __nv_bfloat16 *A, *B;
    if (MODE == 0) {
        A = g_wb + (size_t)which * CH * CH + (size_t)m0 * CH;
        B = g_hnb + (size_t)z * CH * HW + n0;
    } else {
        A = g_wpb + (size_t)m0 * CH;
        B = g_aob + (size_t)z * CH * HW + n0;
    }

    extern __shared__ __align__(16) char smem[];
    uint32_t sb = smem_u32(smem);
    int t = threadIdx.x, wid = t >> 5, lane = t & 31;
    int wm = wid >> 2, wn = wid & 3;

    float acc[4][4][4];
#pragma unroll
    for (int i = 0; i < 4; i++)
#pragma unroll
        for (int j = 0; j < 4; j++)
#pragma unroll
            for (int r = 0; r < 4; r++) acc[i][j][r] = 0.f;

    fill_tile<false>(A, CH, sb, t);
    fill_tile<true>(B, HW, sb + TILE_N, t);
    CP_COMMIT();

#pragma unroll 1
    for (int c = 0; c < NC; c++) {
        int buf = c & 1;
        if (c + 1 < NC) {
            uint32_t nb = sb + ((c + 1) & 1) * STAGE;
            fill_tile<false>(A + (c + 1) * KCH, CH, nb, t);
            fill_tile<true>(B + (size_t)(c + 1) * KCH * HW, HW, nb + TILE_N, t);
            CP_COMMIT();
            CP_WAIT1();
        } else {
            CP_WAIT0();
        }
        __syncthreads();

        uint32_t ab = sb + buf * STAGE;
        uint32_t bb = ab + TILE_N;
#pragma unroll
        for (int ks = 0; ks < KCH / 16; ks++) {
            uint32_t a_frag[4][4];
            uint32_t b_frag[4][2];
#pragma unroll
            for (int mt = 0; mt < 4; mt++) {
                int row = wm * 64 + mt * 16 + (lane & 15);
                ldsm_x4(a_frag[mt], ab + row * ROW_N + (ks * 16 + (lane >> 4) * 8) * 2);
            }
#pragma unroll
            for (int p = 0; p < 2; p++) {
                int krow = (lane & 7) + ((lane >> 4) << 3) + ks * 16;
                int ncol = wn * 32 + p * 16 + ((lane >> 3) & 1) * 8;
                uint32_t q[4];
                ldsm_x4_t(q, bb + krow * ROW_T + ncol * 2);
                b_frag[2 * p][0]     = q[0]; b_frag[2 * p][1]     = q[2];
                b_frag[2 * p + 1][0] = q[1]; b_frag[2 * p + 1][1] = q[3];
            }
#pragma unroll
            for (int mt = 0; mt < 4; mt++)
#pragma unroll
                for (int nt = 0; nt < 4; nt++)
                    mma_bf16(acc[mt][nt], a_frag[mt], b_frag[nt]);
        }
        __syncthreads();
    }

    int r0 = m0 + wm * 64 + (lane >> 2);
    int c0 = n0 + wn * 32 + (lane & 3) * 2;

    if (MODE == 0) {
        __half* D = ((which == 0) ? g_q2 : (which == 1) ? g_k2 : g_v2) + (size_t)z * CH * HW;
        const float* bias = (which == 0) ? bias0 : (which == 1) ? bias1 : bias2;
#pragma unroll
        for (int mt = 0; mt < 4; mt++) {
            int r = r0 + mt * 16;
            float b1 = bias[r], b2 = bias[r + 8];
#pragma unroll
            for (int nt = 0; nt < 4; nt++) {
                size_t base = (size_t)r * HW + c0 + nt * 8;
                *(__half2*)&D[base] =
                    __floats2half2_rn(acc[mt][nt][0] + b1, acc[mt][nt][1] + b1);
                *(__half2*)&D[base + 8 * HW] =
                    __floats2half2_rn(acc[mt][nt][2] + b2, acc[mt][nt][3] + b2);
            }
        }
    } else {
#pragma unroll
        for (int mt = 0; mt < 4; mt++) {
            int r = r0 + mt * 16;
            float b1 = bias0[r], b2 = bias0[r + 8];
#pragma unroll
            for (int nt = 0; nt < 4; nt++) {
                size_t idx = ((size_t)z * CH + r) * HW + c0 + nt * 8;
                float2 x0 = *(const float2*)&xres[idx];
                float2 x1 = *(const float2*)&xres[idx + 8 * HW];
                float2 v0 = {acc[mt][nt][0] + b1 + x0.x, acc[mt][nt][1] + b1 + x0.y};
                float2 v1 = {acc[mt][nt][2] + b2 + x1.x, acc[mt][nt][3] + b2 + x1.y};
                *(float2*)&outp[idx]          = v0;
                *(float2*)&outp[idx + 8 * HW] = v1;
            }
        }
    }
}

// ================= weights fp32 -> bf16 (tiny, once per call) ===============
__global__ void __launch_bounds__(256) wconv_kernel(const float* __restrict__ wq,
                                                    const float* __restrict__ wk,
                                                    const float* __restrict__ wv,
                                                    const float* __restrict__ wp) {
    int i = blockIdx.x * 256 + threadIdx.x;      // 16384 float4s per matrix
    const float* srcs[4] = {wq, wk, wv, wp};
    __nv_bfloat16* dsts[4] = {g_wb, g_wb + CH * CH, g_wb + 2 * CH * CH, g_wpb};
#pragma unroll
    for (int m = 0; m < 4; m++) {
        float4 a = ((const float4*)srcs[m])[i];
        __nv_bfloat162 p0 = __float22bfloat162_rn(make_float2(a.x, a.y));
        __nv_bfloat162 p1 = __float22bfloat162_rn(make_float2(a.z, a.w));
        uint2 pk = {*(uint32_t*)&p0, *(uint32_t*)&p1};
        *(uint2*)&dsts[m][i * 4] = pk;
    }
}

// ============================ GroupNorm -> bf16 =============================
__global__ void __launch_bounds__(256) gn_kernel(const float* __restrict__ x,
                                                 const float* __restrict__ sc,
                                                 const float* __restrict__ bi) {
    int b = blockIdx.x >> 5;
    int g = blockIdx.x & 31;
    const float* xp = x + ((size_t)b * CH + g * CPG) * HW;
    __nv_bfloat16* op = g_hnb + ((size_t)b * CH + g * CPG) * HW;
    int t = threadIdx.x;
    const int TOT = CPG * HW;

    float s = 0.f, s2 = 0.f;
    for (int i = t * 4; i < TOT; i += 1024) {
        float4 v = *(const float4*)&xp[i];
        s  += v.x + v.y + v.z + v.w;
        s2 += v.x * v.x + v.y * v.y + v.z * v.z + v.w * v.w;
    }
    __shared__ float rs[256], rs2[256];
    rs[t] = s; rs2[t] = s2;
    __syncthreads();
    for (int o = 128; o > 0; o >>= 1) {
        if (t < o) { rs[t] += rs[t + o]; rs2[t] += rs2[t + o]; }
        __syncthreads();
    }
    float mean = rs[0] * (1.0f / TOT);
    float var  = rs2[0] * (1.0f / TOT) - mean * mean;
    float inv  = rsqrtf(var + 1e-6f);

    for (int i = t * 4; i < TOT; i += 1024) {
        int c = g * CPG + (i >> 12);
        float a  = sc[c] * inv;
        float bb = bi[c] - mean * a;
        float4 v = *(const float4*)&xp[i];
        __nv_bfloat162 p0 = __float22bfloat162_rn(make_float2(v.x * a + bb, v.y * a + bb));
        __nv_bfloat162 p1 = __float22bfloat162_rn(make_float2(v.z * a + bb, v.w * a + bb));
        uint2 pk = {*(uint32_t*)&p0, *(uint32_t*)&p1};
        *(uint2*)&op[i] = pk;
    }
}

// ============== Row softmax over m: reads fp16 S, writes fp16 P =============
__global__ void __launch_bounds__(256) softmax_kernel() {
    size_t row = blockIdx.x;                 // b*4096 + n
    const __half* p = g_s + row * (size_t)HW;
    __half* q = g_p + row * (size_t)HW;
    int t = threadIdx.x;

    uint4 raw[2];
    float v[16];
    float mx = -1e30f;
#pragma unroll
    for (int j = 0; j < 2; j++) {
        raw[j] = *(const uint4*)&p[t * 8 + j * 2048];
        const uint32_t* w = (const uint32_t*)&raw[j];
#pragma unroll
        for (int h = 0; h < 4; h++) {
            float2 f = __half22float2(*(const __half2*)&w[h]);
            v[j * 8 + h * 2]     = f.x;
            v[j * 8 + h * 2 + 1] = f.y;
            mx = fmaxf(mx, fmaxf(f.x, f.y));
        }
    }
    __shared__ float red[256];
    red[t] = mx; __syncthreads();
    for (int o = 128; o > 0; o >>= 1) {
        if (t < o) red[t] = fmaxf(red[t], red[t + o]);
        __syncthreads();
    }
    mx = red[0];
    __syncthreads();

    float sum = 0.f;
#pragma unroll
    for (int i = 0; i < 16; i++) { v[i] = __expf(v[i] - mx); sum += v[i]; }
    red[t] = sum; __syncthreads();
    for (int o = 128; o > 0; o >>= 1) {
        if (t < o) red[t] += red[t + o];
        __syncthreads();
    }
    float inv = 1.0f / red[0];
#pragma unroll
    for (int j = 0; j < 2; j++) {
        uint32_t w[4];
#pragma unroll
        for (int h = 0; h < 4; h++) {
            __half2 o2 = __floats2half2_rn(v[j * 8 + h * 2] * inv, v[j * 8 + h * 2 + 1] * inv);
            w[h] = *(uint32_t*)&o2;
        }
        *(uint4*)&q[t * 8 + j * 2048] = *(uint4*)w;
    }
}

// ============================== launch ======================================
extern "C" void kernel_launch(void* const* d_in, const int* in_sizes, int n_in,
                              void* d_out, int out_size) {
    const float* x    = (const float*)d_in[0];
    const float* gns  = (const float*)d_in[1];
    const float* gnb  = (const float*)d_in[2];
    const float* wq   = (const float*)d_in[3];
    const float* bq   = (const float*)d_in[4];
    const float* wk   = (const float*)d_in[5];
    const float* bk   = (const float*)d_in[6];
    const float* wv   = (const float*)d_in[7];
    const float* bv   = (const float*)d_in[8];
    const float* wp   = (const float*)d_in[9];
    const float* bp   = (const float*)d_in[10];
    float* out = (float*)d_out;

    constexpr int SM_BF   = 2 * (TILE_N + TILE_T);  // 71680 (qkv/proj, 2-stage)
    constexpr int SM_SC   = 2 * (2 * TILE_T);       // 69632 (scores, 2-stage)
    constexpr int SM_PV   = 2 * (2 * TILE_N);       // 73728 (PV, 2-stage)

    cudaFuncSetAttribute(gemm_bf16<0>, cudaFuncAttributeMaxDynamicSharedMemorySize, SM_BF);
    cudaFuncSetAttribute(gemm_bf16<3>, cudaFuncAttributeMaxDynamicSharedMemorySize, SM_BF);
    cudaFuncSetAttribute(gemm_f16<1>,  cudaFuncAttributeMaxDynamicSharedMemorySize, SM_SC);
    cudaFuncSetAttribute(gemm_f16<2>,  cudaFuncAttributeMaxDynamicSharedMemorySize, SM_PV);

    gn_kernel<<<BSZ * 32, 256>>>(x, gns, gnb);
    wconv_kernel<<<64, 256>>>(wq, wk, wv, wp);
    // QKV: q/k/v[c][n] = W hn + b  -> fp16
    gemm_bf16<0><<<dim3(HW / 128, 6, BSZ), 256, SM_BF>>>(bq, bk, bv, nullptr, nullptr);
    // scores: S[n][m] = q . k / 16  -> fp16 (f16 accum)
    gemm_f16<1><<<dim3(HW / 128, HW / 128, BSZ), 256, SM_SC>>>();
    softmax_kernel<<<BSZ * HW, 256>>>();
    // PV: ao[c][n] = v P^T  -> bf16 (f16 accum; c-tile fastest for L2 pairing)
    gemm_f16<2><<<dim3(CH / 128, HW / 128, BSZ), 256, SM_PV>>>();
    // proj + residual -> fp32
    gemm_bf16<3><<<dim3(HW / 128, CH / 128, BSZ), 256, SM_BF>>>(bp, nullptr, nullptr, x, out);
}

// round 8
// speedup vs baseline: 6.3289x; 1.0314x over previous
#include <cuda_runtime.h>
#include <cuda_bf16.h>
#include <cuda_fp16.h>
#include <cuda_fp8.h>
#include <math.h>
#include <stdint.h>

// Shapes (fixed by the problem)
#define BSZ 8
#define CH  256
#define HW  4096            // 64*64 tokens
#define CPG 8               // channels per group

// ---------------- scratch (static device globals; no runtime alloc) --------
__device__ __nv_bfloat16 g_hnb[(size_t)BSZ * CH * HW];          // groupnormed x, [b][c][n]
__device__ uint8_t       g_q8[(size_t)BSZ * HW * CH];           // q [b][token][c] e4m3
__device__ uint8_t       g_k8[(size_t)BSZ * HW * CH];           // k [b][token][c] e4m3
__device__ __half        g_v2[(size_t)BSZ * CH * HW];           // v [b][c][n] fp16
__device__ __nv_bfloat16 g_aob[(size_t)BSZ * CH * HW];          // attn out [b][c][n] bf16
__device__ __half        g_s [(size_t)BSZ * HW * HW];           // scores fp16 256MB
__device__ __half        g_p [(size_t)BSZ * HW * HW];           // probs fp16 256MB
__device__ __nv_bfloat16 g_wb[3 * CH * CH];                     // wq,wk,wv bf16
__device__ __nv_bfloat16 g_wpb[CH * CH];                        // wproj bf16

// ====================== PTX helpers (sm_80/sm_89 features only) =============
__device__ __forceinline__ uint32_t smem_u32(const void* p) {
    uint32_t a;
    asm("{ .reg .u64 t; cvta.to.shared.u64 t, %1; cvt.u32.u64 %0, t; }" : "=r"(a) : "l"(p));
    return a;
}
__device__ __forceinline__ void ldsm_x4(uint32_t* r, uint32_t addr) {
    asm volatile("ldmatrix.sync.aligned.m8n8.x4.shared.b16 {%0,%1,%2,%3}, [%4];"
        : "=r"(r[0]), "=r"(r[1]), "=r"(r[2]), "=r"(r[3]) : "r"(addr));
}
__device__ __forceinline__ void ldsm_x4_t(uint32_t* r, uint32_t addr) {
    asm volatile("ldmatrix.sync.aligned.m8n8.x4.trans.shared.b16 {%0,%1,%2,%3}, [%4];"
        : "=r"(r[0]), "=r"(r[1]), "=r"(r[2]), "=r"(r[3]) : "r"(addr));
}
__device__ __forceinline__ void mma_bf16(float* d, const uint32_t* a, const uint32_t* b) {
    asm volatile("mma.sync.aligned.m16n8k16.row.col.f32.bf16.bf16.f32 "
        "{%0,%1,%2,%3}, {%4,%5,%6,%7}, {%8,%9}, {%0,%1,%2,%3};"
        : "+f"(d[0]), "+f"(d[1]), "+f"(d[2]), "+f"(d[3])
        : "r"(a[0]), "r"(a[1]), "r"(a[2]), "r"(a[3]), "r"(b[0]), "r"(b[1]));
}
__device__ __forceinline__ void mma_f16(uint32_t* c, const uint32_t* a, const uint32_t* b) {
    asm volatile("mma.sync.aligned.m16n8k16.row.col.f16.f16.f16.f16 "
        "{%0,%1}, {%2,%3,%4,%5}, {%6,%7}, {%0,%1};"
        : "+r"(c[0]), "+r"(c[1])
        : "r"(a[0]), "r"(a[1]), "r"(a[2]), "r"(a[3]), "r"(b[0]), "r"(b[1]));
}
// fp8 e4m3 x e4m3 -> f16 accum, k=32
__device__ __forceinline__ void mma_fp8(uint32_t* c, const uint32_t* a, const uint32_t* b) {
    asm volatile("mma.sync.aligned.m16n8k32.row.col.f16.e4m3.e4m3.f16 "
        "{%0,%1}, {%2,%3,%4,%5}, {%6,%7}, {%0,%1};"
        : "+r"(c[0]), "+r"(c[1])
        : "r"(a[0]), "r"(a[1]), "r"(a[2]), "r"(a[3]), "r"(b[0]), "r"(b[1]));
}
#define CP_ASYNC16(s, g) asm volatile("cp.async.cg.shared.global [%0], [%1], 16;" :: "r"(s), "l"(g))
#define CP_COMMIT()      asm volatile("cp.async.commit_group;" ::: "memory")
#define CP_WAIT1()       asm volatile("cp.async.wait_group 1;" ::: "memory")
#define CP_WAIT0()       asm volatile("cp.async.wait_group 0;" ::: "memory")

// 16-bit tile geometry, K-chunk = 64 elements.
static constexpr int ROW_N  = 144;           // 128B data + 16 pad
static constexpr int ROW_T  = 272;           // 256B data + 16 pad
static constexpr int TILE_N = 128 * ROW_N;   // 18432
static constexpr int TILE_T = 64 * ROW_T;    // 17408
static constexpr int KCH    = 64;
// fp8 tile: 128 rows x 128 k-bytes, padded stride 144B
static constexpr int ROW_8  = 144;
static constexpr int TILE_8 = 128 * ROW_8;   // 18432
static constexpr int KCH8   = 128;           // k-bytes per chunk

template <bool TR, typename T>
__device__ __forceinline__ void fill_tile(const T* __restrict__ g,
                                          size_t stride, uint32_t sbase, int t) {
#pragma unroll
    for (int it = 0; it < 4; it++) {
        int chunk = t + it * 256;           // 1024 chunks of 16B
        if (TR) {
            int row = chunk >> 4, c16 = chunk & 15;
            CP_ASYNC16(sbase + row * ROW_T + c16 * 16,
                       g + (size_t)row * stride + c16 * 8);
        } else {
            int row = chunk >> 3, c16 = chunk & 7;
            CP_ASYNC16(sbase + row * ROW_N + c16 * 16,
                       g + (size_t)row * stride + c16 * 8);
        }
    }
}
// fp8: 128 rows x 128 bytes; stride/gmem offsets in BYTES
__device__ __forceinline__ void fill_tile8(const uint8_t* __restrict__ g,
                                           size_t stride, uint32_t sbase, int t) {
#pragma unroll
    for (int it = 0; it < 4; it++) {
        int chunk = t + it * 256;           // 1024 chunks of 16B
        int row = chunk >> 3, c16 = chunk & 7;
        CP_ASYNC16(sbase + row * ROW_8 + c16 * 16,
                   g + (size_t)row * stride + c16 * 16);
    }
}

// ==================== FP8 scores GEMM =======================================
// S[n][m] = (1/16) sum_c q[n][c] k[m][c]; q,k e4m3 [token][c]; f16 acc -> fp16.
// CTA 128x128, warps 2(m)x4(n); K=256 bytes = 2 chunks of 128.
__global__ void __launch_bounds__(256, 3) gemm_scores8() {
    constexpr int NC = CH / KCH8;            // 2
    constexpr int STAGE = 2 * TILE_8;        // 36864

    int z = blockIdx.z;
    int m0 = blockIdx.y * 128, n0 = blockIdx.x * 128;
    const uint8_t* A = g_q8 + (size_t)z * HW * CH + (size_t)m0 * CH;
    const uint8_t* B = g_k8 + (size_t)z * HW * CH + (size_t)n0 * CH;

    extern __shared__ __align__(16) char smem[];
    uint32_t sb = smem_u32(smem);
    int t = threadIdx.x, wid = t >> 5, lane = t & 31;
    int wm = wid >> 2, wn = wid & 3;

    uint32_t acc[4][4][2];
#pragma unroll
    for (int i = 0; i < 4; i++)
#pragma unroll
        for (int j = 0; j < 4; j++) { acc[i][j][0] = 0u; acc[i][j][1] = 0u; }

    fill_tile8(A, CH, sb, t);
    fill_tile8(B, CH, sb + TILE_8, t);
    CP_COMMIT();

#pragma unroll 1
    for (int c = 0; c < NC; c++) {
        int buf = c & 1;
        if (c + 1 < NC) {
            uint32_t nb = sb + ((c + 1) & 1) * STAGE;
            fill_tile8(A + (c + 1) * KCH8, CH, nb, t);
            fill_tile8(B + (c + 1) * KCH8, CH, nb + TILE_8, t);
            CP_COMMIT();
            CP_WAIT1();
        } else {
            CP_WAIT0();
        }
        __syncthreads();

        uint32_t ab = sb + buf * STAGE;
        uint32_t bb = ab + TILE_8;
#pragma unroll
        for (int ks = 0; ks < 4; ks++) {     // 4 x k32 per 128B chunk
            uint32_t a_frag[4][4];
            uint32_t b_frag[4][2];
#pragma unroll
            for (int mt = 0; mt < 4; mt++) {
                int row = wm * 64 + mt * 16 + (lane & 15);
                ldsm_x4(a_frag[mt], ab + row * ROW_8 + ks * 32 + (lane >> 4) * 16);
            }
#pragma unroll
            for (int p = 0; p < 2; p++) {
                int row = wn * 32 + p * 16 + (lane & 15);
                uint32_t q[4];
                ldsm_x4(q, bb + row * ROW_8 + ks * 32 + (lane >> 4) * 16);
                b_frag[2 * p][0]     = q[0]; b_frag[2 * p][1]     = q[2];
                b_frag[2 * p + 1][0] = q[1]; b_frag[2 * p + 1][1] = q[3];
            }
#pragma unroll
            for (int mt = 0; mt < 4; mt++)
#pragma unroll
                for (int nt = 0; nt < 4; nt++)
                    mma_fp8(acc[mt][nt], a_frag[mt], b_frag[nt]);
        }
        __syncthreads();
    }

    int r0 = m0 + wm * 64 + (lane >> 2);
    int c0 = n0 + wn * 32 + (lane & 3) * 2;
    __half* D = g_s + (size_t)z * HW * HW;
    const __half2 sc = __half2half2(__float2half(0.0625f));
#pragma unroll
    for (int mt = 0; mt < 4; mt++)
#pragma unroll
        for (int nt = 0; nt < 4; nt++) {
            size_t base = (size_t)(r0 + mt * 16) * HW + c0 + nt * 8;
            *(__half2*)&D[base]          = __hmul2(*(__half2*)&acc[mt][nt][0], sc);
            *(__half2*)&D[base + 8 * HW] = __hmul2(*(__half2*)&acc[mt][nt][1], sc);
        }
}

// ============= q/k GEMM (transposed): D[token][o] = hn^T * W^T, e4m3 ========
// A = hn [c][token] (trans ldsm), B = W [o][c] (normal ldsm), bf16/f32 acc.
// grid (32 token-tiles, 2 o-tiles, 16 = b*2 + which)
__global__ void __launch_bounds__(256) gemm_qk(const float* __restrict__ bq,
                                               const float* __restrict__ bk) {
    constexpr int NC = CH / KCH;             // 4
    constexpr int STAGE = TILE_T + TILE_N;

    int zz = blockIdx.z;
    int z = zz >> 1, which = zz & 1;
    int m0 = blockIdx.x * 128;               // token tile
    int n0 = blockIdx.y * 128;               // out-channel tile
    const __nv_bfloat16* A = g_hnb + (size_t)z * CH * HW + m0;
    const __nv_bfloat16* B = g_wb + (size_t)which * CH * CH + (size_t)n0 * CH;
    const float* bias = which ? bk : bq;
    uint8_t* D = (which ? g_k8 : g_q8) + (size_t)z * HW * CH;

    extern __shared__ __align__(16) char smem[];
    uint32_t sb = smem_u32(smem);
    int t = threadIdx.x, wid = t >> 5, lane = t & 31;
    int wm = wid >> 2, wn = wid & 3;

    float acc[4][4][4];
#pragma unroll
    for (int i = 0; i < 4; i++)
#pragma unroll
        for (int j = 0; j < 4; j++)
#pragma unroll
            for (int r = 0; r < 4; r++) acc[i][j][r] = 0.f;

    fill_tile<true>(A, HW, sb, t);
    fill_tile<false>(B, CH, sb + TILE_T, t);
    CP_COMMIT();

#pragma unroll 1
    for (int c = 0; c < NC; c++) {
        int buf = c & 1;
        if (c + 1 < NC) {
            uint32_t nb = sb + ((c + 1) & 1) * STAGE;
            fill_tile<true>(A + (size_t)(c + 1) * KCH * HW, HW, nb, t);
            fill_tile<false>(B + (c + 1) * KCH, CH, nb + TILE_T, t);
            CP_COMMIT();
            CP_WAIT1();
        } else {
            CP_WAIT0();
        }
        __syncthreads();

        uint32_t ab = sb + buf * STAGE;
        uint32_t bb = ab + TILE_T;
#pragma unroll
        for (int ks = 0; ks < KCH / 16; ks++) {
            uint32_t a_frag[4][4];
            uint32_t b_frag[4][2];
#pragma unroll
            for (int mt = 0; mt < 4; mt++) {
                int krow = (lane & 7) + ((lane >> 4) << 3) + ks * 16;
                int mcol = wm * 64 + mt * 16 + ((lane >> 3) & 1) * 8;
                ldsm_x4_t(a_frag[mt], ab + krow * ROW_T + mcol * 2);
            }
#pragma unroll
            for (int p = 0; p < 2; p++) {
                int row = wn * 32 + p * 16 + (lane & 15);
                uint32_t q[4];
                ldsm_x4(q, bb + row * ROW_N + (ks * 16 + (lane >> 4) * 8) * 2);
                b_frag[2 * p][0]     = q[0]; b_frag[2 * p][1]     = q[2];
                b_frag[2 * p + 1][0] = q[1]; b_frag[2 * p + 1][1] = q[3];
            }
#pragma unroll
            for (int mt = 0; mt < 4; mt++)
#pragma unroll
                for (int nt = 0; nt < 4; nt++)
                    mma_bf16(acc[mt][nt], a_frag[mt], b_frag[nt]);
        }
        __syncthreads();
    }

    int r0 = m0 + wm * 64 + (lane >> 2);     // token
    int c0 = n0 + wn * 32 + (lane & 3) * 2;  // out channel
    float bn[8];
#pragma unroll
    for (int nt = 0; nt < 4; nt++) {
        bn[2 * nt]     = bias[c0 + nt * 8];
        bn[2 * nt + 1] = bias[c0 + nt * 8 + 1];
    }
#pragma unroll
    for (int mt = 0; mt < 4; mt++) {
        int r = r0 + mt * 16;
#pragma unroll
        for (int nt = 0; nt < 4; nt++) {
            __nv_fp8x2_e4m3 p0(make_float2(acc[mt][nt][0] + bn[2 * nt],
                                           acc[mt][nt][1] + bn[2 * nt + 1]));
            __nv_fp8x2_e4m3 p1(make_float2(acc[mt][nt][2] + bn[2 * nt],
                                           acc[mt][nt][3] + bn[2 * nt + 1]));
            *(unsigned short*)&D[(size_t)r * CH + c0 + nt * 8]       = *(unsigned short*)&p0;
            *(unsigned short*)&D[(size_t)(r + 8) * CH + c0 + nt * 8] = *(unsigned short*)&p1;
        }
    }
}

// ============= v GEMM: v[c][n] = Wv hn + b -> fp16 (A normal, B trans) ======
__global__ void __launch_bounds__(256) gemm_v(const float* __restrict__ bv) {
    constexpr int NC = CH / KCH;
    constexpr int STAGE = TILE_N + TILE_T;

    int z = blockIdx.z;
    int n0 = blockIdx.x * 128, m0 = blockIdx.y * 128;
    const __nv_bfloat16* A = g_wb + (size_t)2 * CH * CH + (size_t)m0 * CH;
    const __nv_bfloat16* B = g_hnb + (size_t)z * CH * HW + n0;

    extern __shared__ __align__(16) char smem[];
    uint32_t sb = smem_u32(smem);
    int t = threadIdx.x, wid = t >> 5, lane = t & 31;
    int wm = wid >> 2, wn = wid & 3;

    float acc[4][4][4];
#pragma unroll
    for (int i = 0; i < 4; i++)
#pragma unroll
        for (int j = 0; j < 4; j++)
#pragma unroll
            for (int r = 0; r < 4; r++) acc[i][j][r] = 0.f;

    fill_tile<false>(A, CH, sb, t);
    fill_tile<true>(B, HW, sb + TILE_N, t);
    CP_COMMIT();

#pragma unroll 1
    for (int c = 0; c < NC; c++) {
        int buf = c & 1;
        if (c + 1 < NC) {
            uint32_t nb = sb + ((c + 1) & 1) * STAGE;
            fill_tile<false>(A + (c + 1) * KCH, CH, nb, t);
            fill_tile<true>(B + (size_t)(c + 1) * KCH * HW, HW, nb + TILE_N, t);
            CP_COMMIT();
            CP_WAIT1();
        } else {
            CP_WAIT0();
        }
        __syncthreads();

        uint32_t ab = sb + buf * STAGE;
        uint32_t bb = ab + TILE_N;
#pragma unroll
        for (int ks = 0; ks < KCH / 16; ks++) {
            uint32_t a_frag[4][4];
            uint32_t b_frag[4][2];
#pragma unroll
            for (int mt = 0; mt < 4; mt++) {
                int row = wm * 64 + mt * 16 + (lane & 15);
                ldsm_x4(a_frag[mt], ab + row * ROW_N + (ks * 16 + (lane >> 4) * 8) * 2);
            }
#pragma unroll
            for (int p = 0; p < 2; p++) {
                int krow = (lane & 7) + ((lane >> 4) << 3) + ks * 16;
                int ncol = wn * 32 + p * 16 + ((lane >> 3) & 1) * 8;
                uint32_t q[4];
                ldsm_x4_t(q, bb + krow * ROW_T + ncol * 2);
                b_frag[2 * p][0]     = q[0]; b_frag[2 * p][1]     = q[2];
                b_frag[2 * p + 1][0] = q[1]; b_frag[2 * p + 1][1] = q[3];
            }
#pragma unroll
            for (int mt = 0; mt < 4; mt++)
#pragma unroll
                for (int nt = 0; nt < 4; nt++)
                    mma_bf16(acc[mt][nt], a_frag[mt], b_frag[nt]);
        }
        __syncthreads();
    }

    int r0 = m0 + wm * 64 + (lane >> 2);
    int c0 = n0 + wn * 32 + (lane & 3) * 2;
    __half* D = g_v2 + (size_t)z * CH * HW;
#pragma unroll
    for (int mt = 0; mt < 4; mt++) {
        int r = r0 + mt * 16;
        float b1 = bv[r], b2 = bv[r + 8];
#pragma unroll
        for (int nt = 0; nt < 4; nt++) {
            size_t base = (size_t)r * HW + c0 + nt * 8;
            *(__half2*)&D[base]          = __floats2half2_rn(acc[mt][nt][0] + b1, acc[mt][nt][1] + b1);
            *(__half2*)&D[base + 8 * HW] = __floats2half2_rn(acc[mt][nt][2] + b2, acc[mt][nt][3] + b2);
        }
    }
}

// ============= PV (f16 acc): ao[c][n] = v[c][m] * P[n][m] -> bf16 ===========
__global__ void __launch_bounds__(256, 3) gemm_pv() {
    constexpr int NC = HW / KCH;             // 64
    constexpr int STAGE = 2 * TILE_N;

    int z = blockIdx.z;
    int m0 = blockIdx.x * 128, n0 = blockIdx.y * 128;   // c-tile fastest: L2 pairing on P
    const __half* A = g_v2 + (size_t)z * CH * HW + (size_t)m0 * HW;
    const __half* B = g_p  + (size_t)z * HW * HW + (size_t)n0 * HW;

    extern __shared__ __align__(16) char smem[];
    uint32_t sb = smem_u32(smem);
    int t = threadIdx.x, wid = t >> 5, lane = t & 31;
    int wm = wid >> 2, wn = wid & 3;

    uint32_t acc[4][4][2];
#pragma unroll
    for (int i = 0; i < 4; i++)
#pragma unroll
        for (int j = 0; j < 4; j++) { acc[i][j][0] = 0u; acc[i][j][1] = 0u; }

    fill_tile<false>(A, HW, sb, t);
    fill_tile<false>(B, HW, sb + TILE_N, t);
    CP_COMMIT();

#pragma unroll 1
    for (int c = 0; c < NC; c++) {
        int buf = c & 1;
        if (c + 1 < NC) {
            uint32_t nb = sb + ((c + 1) & 1) * STAGE;
            fill_tile<false>(A + (c + 1) * KCH, HW, nb, t);
            fill_tile<false>(B + (c + 1) * KCH, HW, nb + TILE_N, t);
            CP_COMMIT();
            CP_WAIT1();
        } else {
            CP_WAIT0();
        }
        __syncthreads();

        uint32_t ab = sb + buf * STAGE;
        uint32_t bb = ab + TILE_N;
#pragma unroll
        for (int ks = 0; ks < KCH / 16; ks++) {
            uint32_t a_frag[4][4];
            uint32_t b_frag[4][2];
#pragma unroll
            for (int mt = 0; mt < 4; mt++) {
                int row = wm * 64 + mt * 16 + (lane & 15);
                ldsm_x4(a_frag[mt], ab + row * ROW_N + (ks * 16 + (lane >> 4) * 8) * 2);
            }
#pragma unroll
            for (int p = 0; p < 2; p++) {
                int row = wn * 32 + p * 16 + (lane & 15);
                uint32_t q[4];
                ldsm_x4(q, bb + row * ROW_N + (ks * 16 + (lane >> 4) * 8) * 2);
                b_frag[2 * p][0]     = q[0]; b_frag[2 * p][1]     = q[2];
                b_frag[2 * p + 1][0] = q[1]; b_frag[2 * p + 1][1] = q[3];
            }
#pragma unroll
            for (int mt = 0; mt < 4; mt++)
#pragma unroll
                for (int nt = 0; nt < 4; nt++)
                    mma_f16(acc[mt][nt], a_frag[mt], b_frag[nt]);
        }
        __syncthreads();
    }

    int r0 = m0 + wm * 64 + (lane >> 2);
    int c0 = n0 + wn * 32 + (lane & 3) * 2;
    __nv_bfloat16* D = g_aob + (size_t)z * CH * HW;
#pragma unroll
    for (int mt = 0; mt < 4; mt++)
#pragma unroll
        for (int nt = 0; nt < 4; nt++) {
            size_t base = (size_t)(r0 + mt * 16) * HW + c0 + nt * 8;
            float2 f0 = __half22float2(*(__half2*)&acc[mt][nt][0]);
            float2 f1 = __half22float2(*(__half2*)&acc[mt][nt][1]);
            *(__nv_bfloat162*)&D[base]          = __float22bfloat162_rn(f0);
            *(__nv_bfloat162*)&D[base + 8 * HW] = __float22bfloat162_rn(f1);
        }
}

// ============= proj + residual: out = x + Wp * ao + bp -> fp32 ==============
__global__ void __launch_bounds__(256) gemm_proj(const float* __restrict__ bp,
                                                 const float* __restrict__ xres,
                                                 float* __restrict__ outp) {
    constexpr int NC = CH / KCH;
    constexpr int STAGE = TILE_N + TILE_T;

    int z = blockIdx.z;
    int n0 = blockIdx.x * 128, m0 = blockIdx.y * 128;
    const __nv_bfloat16* A = g_wpb + (size_t)m0 * CH;
    const __nv_bfloat16* B = g_aob + (size_t)z * CH * HW + n0;

    extern __shared__ __align__(16) char smem[];
    uint32_t sb = smem_u32(smem);
    int t = threadIdx.x, wid = t >> 5, lane = t & 31;
    int wm = wid >> 2, wn = wid & 3;

    float acc[4][4][4];
#pragma unroll
    for (int i = 0; i < 4; i++)
#pragma unroll
        for (int j = 0; j < 4; j++)
#pragma unroll
            for (int r = 0; r < 4; r++) acc[i][j][r] = 0.f;

    fill_tile<false>(A, CH, sb, t);
    fill_tile<true>(B, HW, sb + TILE_N, t);
    CP_COMMIT();

#pragma unroll 1
    for (int c = 0; c < NC; c++) {
        int buf = c & 1;
        if (c + 1 < NC) {
            uint32_t nb = sb + ((c + 1) & 1) * STAGE;
            fill_tile<false>(A + (c + 1) * KCH, CH, nb, t);
            fill_tile<true>(B + (size_t)(c + 1) * KCH * HW, HW, nb + TILE_N, t);
            CP_COMMIT();
            CP_WAIT1();
        } else {
            CP_WAIT0();
        }
        __syncthreads();

        uint32_t ab = sb + buf * STAGE;
        uint32_t bb = ab + TILE_N;
#pragma unroll
        for (int ks = 0; ks < KCH / 16; ks++) {
            uint32_t a_frag[4][4];
            uint32_t b_frag[4][2];
#pragma unroll
            for (int mt = 0; mt < 4; mt++) {
                int row = wm * 64 + mt * 16 + (lane & 15);
                ldsm_x4(a_frag[mt], ab + row * ROW_N + (ks * 16 + (lane >> 4) * 8) * 2);
            }
#pragma unroll
            for (int p = 0; p < 2; p++) {
                int krow = (lane & 7) + ((lane >> 4) << 3) + ks * 16;
                int ncol = wn * 32 + p * 16 + ((lane >> 3) & 1) * 8;
                uint32_t q[4];
                ldsm_x4_t(q, bb + krow * ROW_T + ncol * 2);
                b_frag[2 * p][0]     = q[0]; b_frag[2 * p][1]     = q[2];
                b_frag[2 * p + 1][0] = q[1]; b_frag[2 * p + 1][1] = q[3];
            }
#pragma unroll
            for (int mt = 0; mt < 4; mt++)
#pragma unroll
                for (int nt = 0; nt < 4; nt++)
                    mma_bf16(acc[mt][nt], a_frag[mt], b_frag[nt]);
        }
        __syncthreads();
    }

    int r0 = m0 + wm * 64 + (lane >> 2);
    int c0 = n0 + wn * 32 + (lane & 3) * 2;
#pragma unroll
    for (int mt = 0; mt < 4; mt++) {
        int r = r0 + mt * 16;
        float b1 = bp[r], b2 = bp[r + 8];
#pragma unroll
        for (int nt = 0; nt < 4; nt++) {
            size_t idx = ((size_t)z * CH + r) * HW + c0 + nt * 8;
            float2 x0 = *(const float2*)&xres[idx];
            float2 x1 = *(const float2*)&xres[idx + 8 * HW];
            float2 v0 = {acc[mt][nt][0] + b1 + x0.x, acc[mt][nt][1] + b1 + x0.y};
            float2 v1 = {acc[mt][nt][2] + b2 + x1.x, acc[mt][nt][3] + b2 + x1.y};
            *(float2*)&outp[idx]          = v0;
            *(float2*)&outp[idx + 8 * HW] = v1;
        }
    }
}

// ================= weights fp32 -> bf16 (tiny, once per call) ===============
__global__ void __launch_bounds__(256) wconv_kernel(const float* __restrict__ wq,
                                                    const float* __restrict__ wk,
                                                    const float* __restrict__ wv,
                                                    const float* __restrict__ wp) {
    int i = blockIdx.x * 256 + threadIdx.x;
    const float* srcs[4] = {wq, wk, wv, wp};
    __nv_bfloat16* dsts[4] = {g_wb, g_wb + CH * CH, g_wb + 2 * CH * CH, g_wpb};
#pragma unroll
    for (int m = 0; m < 4; m++) {
        float4 a = ((const float4*)srcs[m])[i];
        __nv_bfloat162 p0 = __float22bfloat162_rn(make_float2(a.x, a.y));
        __nv_bfloat162 p1 = __float22bfloat162_rn(make_float2(a.z, a.w));
        uint2 pk = {*(uint32_t*)&p0, *(uint32_t*)&p1};
        *(uint2*)&dsts[m][i * 4] = pk;
    }
}

// ============================ GroupNorm -> bf16 =============================
__global__ void __launch_bounds__(256) gn_kernel(const float* __restrict__ x,
                                                 const float* __restrict__ sc,
                                                 const float* __restrict__ bi) {
    int b = blockIdx.x >> 5;
    int g = blockIdx.x & 31;
    const float* xp = x + ((size_t)b * CH + g * CPG) * HW;
    __nv_bfloat16* op = g_hnb + ((size_t)b * CH + g * CPG) * HW;
    int t = threadIdx.x;
    const int TOT = CPG * HW;

    float s = 0.f, s2 = 0.f;
    for (int i = t * 4; i < TOT; i += 1024) {
        float4 v = *(const float4*)&xp[i];
        s  += v.x + v.y + v.z + v.w;
        s2 += v.x * v.x + v.y * v.y + v.z * v.z + v.w * v.w;
    }
    __shared__ float rs[256], rs2[256];
    rs[t] = s; rs2[t] = s2;
    __syncthreads();
    for (int o = 128; o > 0; o >>= 1) {
        if (t < o) { rs[t] += rs[t + o]; rs2[t] += rs2[t + o]; }
        __syncthreads();
    }
    float mean = rs[0] * (1.0f / TOT);
    float var  = rs2[0] * (1.0f / TOT) - mean * mean;
    float inv  = rsqrtf(var + 1e-6f);

    for (int i = t * 4; i < TOT; i += 1024) {
        int c = g * CPG + (i >> 12);
        float a  = sc[c] * inv;
        float bb = bi[c] - mean * a;
        float4 v = *(const float4*)&xp[i];
        __nv_bfloat162 p0 = __float22bfloat162_rn(make_float2(v.x * a + bb, v.y * a + bb));
        __nv_bfloat162 p1 = __float22bfloat162_rn(make_float2(v.z * a + bb, v.w * a + bb));
        uint2 pk = {*(uint32_t*)&p0, *(uint32_t*)&p1};
        *(uint2*)&op[i] = pk;
    }
}

// ============== Row softmax over m: reads fp16 S, writes fp16 P =============
__global__ void __launch_bounds__(256) softmax_kernel() {
    size_t row = blockIdx.x;                 // b*4096 + n
    const __half* p = g_s + row * (size_t)HW;
    __half* q = g_p + row * (size_t)HW;
    int t = threadIdx.x;

    uint4 raw[2];
    float v[16];
    float mx = -1e30f;
#pragma unroll
    for (int j = 0; j < 2; j++) {
        raw[j] = *(const uint4*)&p[t * 8 + j * 2048];
        const uint32_t* w = (const uint32_t*)&raw[j];
#pragma unroll
        for (int h = 0; h < 4; h++) {
            float2 f = __half22float2(*(const __half2*)&w[h]);
            v[j * 8 + h * 2]     = f.x;
            v[j * 8 + h * 2 + 1] = f.y;
            mx = fmaxf(mx, fmaxf(f.x, f.y));
        }
    }
    __shared__ float red[256];
    red[t] = mx; __syncthreads();
    for (int o = 128; o > 0; o >>= 1) {
        if (t < o) red[t] = fmaxf(red[t], red[t + o]);
        __syncthreads();
    }
    mx = red[0];
    __syncthreads();

    float sum = 0.f;
#pragma unroll
    for (int i = 0; i < 16; i++) { v[i] = __expf(v[i] - mx); sum += v[i]; }
    red[t] = sum; __syncthreads();
    for (int o = 128; o > 0; o >>= 1) {
        if (t < o) red[t] += red[t + o];
        __syncthreads();
    }
    float inv = 1.0f / red[0];
#pragma unroll
    for (int j = 0; j < 2; j++) {
        uint32_t w[4];
#pragma unroll
        for (int h = 0; h < 4; h++) {
            __half2 o2 = __floats2half2_rn(v[j * 8 + h * 2] * inv, v[j * 8 + h * 2 + 1] * inv);
            w[h] = *(uint32_t*)&o2;
        }
        *(uint4*)&q[t * 8 + j * 2048] = *(uint4*)w;
    }
}

// ============================== launch ======================================
extern "C" void kernel_launch(void* const* d_in, const int* in_sizes, int n_in,
                              void* d_out, int out_size) {
    const float* x    = (const float*)d_in[0];
    const float* gns  = (const float*)d_in[1];
    const float* gnb  = (const float*)d_in[2];
    const float* wq   = (const float*)d_in[3];
    const float* bq   = (const float*)d_in[4];
    const float* wk   = (const float*)d_in[5];
    const float* bk   = (const float*)d_in[6];
    const float* wv   = (const float*)d_in[7];
    const float* bv   = (const float*)d_in[8];
    const float* wp   = (const float*)d_in[9];
    const float* bp   = (const float*)d_in[10];
    float* out = (float*)d_out;

    constexpr int SM_BF  = 2 * (TILE_N + TILE_T);  // 71680
    constexpr int SM_SC8 = 2 * (2 * TILE_8);       // 73728
    constexpr int SM_PV  = 2 * (2 * TILE_N);       // 73728

    cudaFuncSetAttribute(gemm_qk,      cudaFuncAttributeMaxDynamicSharedMemorySize, SM_BF);
    cudaFuncSetAttribute(gemm_v,       cudaFuncAttributeMaxDynamicSharedMemorySize, SM_BF);
    cudaFuncSetAttribute(gemm_proj,    cudaFuncAttributeMaxDynamicSharedMemorySize, SM_BF);
    cudaFuncSetAttribute(gemm_scores8, cudaFuncAttributeMaxDynamicSharedMemorySize, SM_SC8);
    cudaFuncSetAttribute(gemm_pv,      cudaFuncAttributeMaxDynamicSharedMemorySize, SM_PV);

    gn_kernel<<<BSZ * 32, 256>>>(x, gns, gnb);
    wconv_kernel<<<64, 256>>>(wq, wk, wv, wp);
    // q,k -> [token][c] e4m3 (transposed GEMM)
    gemm_qk<<<dim3(HW / 128, CH / 128, BSZ * 2), 256, SM_BF>>>(bq, bk);
    // v -> [c][token] fp16
    gemm_v<<<dim3(HW / 128, CH / 128, BSZ), 256, SM_BF>>>(bv);
    // scores (fp8 QMMA): S[n][m] = q.k/16 -> fp16
    gemm_scores8<<<dim3(HW / 128, HW / 128, BSZ), 256, SM_SC8>>>();
    softmax_kernel<<<BSZ * HW, 256>>>();
    // PV (f16 HMMA): ao[c][n] = v P^T -> bf16
    gemm_pv<<<dim3(CH / 128, HW / 128, BSZ), 256, SM_PV>>>();
    // proj + residual -> fp32
    gemm_proj<<<dim3(HW / 128, CH / 128, BSZ), 256, SM_BF>>>(bp, x, out);
}